// round 3
// baseline (speedup 1.0000x reference)
#include <cuda_runtime.h>

// ---------------------------------------------------------------------------
// Problem dims (fixed by the reference)
// ---------------------------------------------------------------------------
#define BATCH  8
#define DMODEL 512
#define QBEF   4096
#define QAFT   1024
#define NKEYS  4096

// ---------------------------------------------------------------------------
// Scratch (device globals; no allocation allowed in kernel_launch)
// ---------------------------------------------------------------------------
__device__ __align__(16) float g_qds[BATCH * QAFT * DMODEL];              // 16 MB
__device__ __align__(16) float g_q  [BATCH * QAFT * DMODEL];              // 16 MB
__device__ __align__(16) float g_k  [BATCH * NKEYS * DMODEL];             // 64 MB
__device__ __align__(16) float g_v  [BATCH * NKEYS * DMODEL];             // 64 MB
__device__ __align__(16) float g_s  [(size_t)BATCH * QAFT * NKEYS];      // 128 MB
__device__ __align__(16) float g_att[BATCH * QAFT * DMODEL];              // 16 MB

// ---------------------------------------------------------------------------
// Generic tiled SGEMM:  C[bz] = scale * A[bz] @ op(B[bz]) + biasM + biasN
//   op(B) = B          (TRANSB=false, B is [K,N] row-major)
//   op(B) = B^T        (TRANSB=true,  B is [N,K] row-major)
// Optional mask epilogue (scores): if mask[m,n] != 0 -> -inf  (mask is int32!)
// Requires: M % 128 == 0, N % 128 == 0, K % 8 == 0 (true for all uses here).
// ---------------------------------------------------------------------------
#define BM 128
#define BN 128
#define BK 8

template <bool TRANSB>
__global__ __launch_bounds__(256)
void sgemm_kernel(const float* __restrict__ A,
                  const float* __restrict__ Bm,
                  float* __restrict__ C,
                  int M, int N, int K,
                  long long sA, long long sB, long long sC,
                  const float* __restrict__ biasN,
                  const float* __restrict__ biasM,
                  float scale,
                  const int* __restrict__ mask,
                  long long sMask)
{
    __shared__ __align__(16) float As[2][BK][BM];
    __shared__ __align__(16) float Bs[2][BK][BN];

    const int tid = threadIdx.x;
    const int bz  = blockIdx.z;

    const float* Ab = A  + (long long)bz * sA;
    const float* Bb = Bm + (long long)bz * sB;
    float*       Cb = C  + (long long)bz * sC;

    const int rowBase = blockIdx.y * BM;
    const int colBase = blockIdx.x * BN;

    // Loader indexing
    const int aRow = tid >> 1;          // 0..127
    const int aCol = (tid & 1) * 4;     // 0 or 4
    const int bRowNN = tid >> 5;        // 0..7
    const int bColNN = (tid & 31) * 4;  // 0..124

    // --- load tile 0 into buffer 0 ---
    {
        float4 va = *(const float4*)(Ab + (long long)(rowBase + aRow) * K + aCol);
        As[0][aCol + 0][aRow] = va.x;
        As[0][aCol + 1][aRow] = va.y;
        As[0][aCol + 2][aRow] = va.z;
        As[0][aCol + 3][aRow] = va.w;
        if (TRANSB) {
            float4 vb = *(const float4*)(Bb + (long long)(colBase + aRow) * K + aCol);
            Bs[0][aCol + 0][aRow] = vb.x;
            Bs[0][aCol + 1][aRow] = vb.y;
            Bs[0][aCol + 2][aRow] = vb.z;
            Bs[0][aCol + 3][aRow] = vb.w;
        } else {
            float4 vb = *(const float4*)(Bb + (long long)bRowNN * N + colBase + bColNN);
            *(float4*)&Bs[0][bRowNN][bColNN] = vb;
        }
    }
    __syncthreads();

    const int ty = tid >> 4;   // 0..15
    const int tx = tid & 15;   // 0..15

    float acc[8][8];
#pragma unroll
    for (int i = 0; i < 8; i++)
#pragma unroll
        for (int j = 0; j < 8; j++) acc[i][j] = 0.0f;

    const int nkt = K / BK;
    float4 pa, pb;

    for (int kt = 0; kt < nkt; ++kt) {
        const int cb = kt & 1;
        const bool more = (kt + 1 < nkt);

        // Prefetch next tile global -> registers
        if (more) {
            const int k0 = (kt + 1) * BK;
            pa = *(const float4*)(Ab + (long long)(rowBase + aRow) * K + k0 + aCol);
            if (TRANSB)
                pb = *(const float4*)(Bb + (long long)(colBase + aRow) * K + k0 + aCol);
            else
                pb = *(const float4*)(Bb + (long long)(k0 + bRowNN) * N + colBase + bColNN);
        }

        // Compute on current buffer
#pragma unroll
        for (int k = 0; k < BK; k++) {
            float a[8], b[8];
            *(float4*)&a[0] = *(const float4*)&As[cb][k][ty * 8];
            *(float4*)&a[4] = *(const float4*)&As[cb][k][ty * 8 + 4];
            *(float4*)&b[0] = *(const float4*)&Bs[cb][k][tx * 8];
            *(float4*)&b[4] = *(const float4*)&Bs[cb][k][tx * 8 + 4];
#pragma unroll
            for (int i = 0; i < 8; i++)
#pragma unroll
                for (int j = 0; j < 8; j++)
                    acc[i][j] = fmaf(a[i], b[j], acc[i][j]);
        }

        // Store prefetched tile into the other buffer
        if (more) {
            const int nb = cb ^ 1;
            As[nb][aCol + 0][aRow] = pa.x;
            As[nb][aCol + 1][aRow] = pa.y;
            As[nb][aCol + 2][aRow] = pa.z;
            As[nb][aCol + 3][aRow] = pa.w;
            if (TRANSB) {
                Bs[nb][aCol + 0][aRow] = pb.x;
                Bs[nb][aCol + 1][aRow] = pb.y;
                Bs[nb][aCol + 2][aRow] = pb.z;
                Bs[nb][aCol + 3][aRow] = pb.w;
            } else {
                *(float4*)&Bs[nb][bRowNN][bColNN] = pb;
            }
            __syncthreads();
        }
    }

    // Epilogue
    const int* maskB = mask ? (mask + (long long)bz * sMask) : nullptr;
#pragma unroll
    for (int i = 0; i < 8; i++) {
        const int r = rowBase + ty * 8 + i;
        const float bm = biasM ? biasM[r] : 0.0f;
        float* crow = Cb + (long long)r * N + colBase + tx * 8;
        const int* mrow = maskB ? (maskB + (long long)r * N + colBase + tx * 8) : nullptr;
#pragma unroll
        for (int j = 0; j < 8; j++) {
            const int c = colBase + tx * 8 + j;
            float v = acc[i][j] * scale + bm;
            if (biasN) v += biasN[c];
            if (mrow && mrow[j] != 0) v = __int_as_float(0xff800000);  // -inf
            crow[j] = v;
        }
    }
}

// ---------------------------------------------------------------------------
// Row softmax over NKEYS=4096 columns, in place. One block (256 thr) per row.
// ---------------------------------------------------------------------------
__global__ __launch_bounds__(256)
void softmax_kernel(float* __restrict__ S)
{
    float* p = S + (long long)blockIdx.x * NKEYS;
    const int tid = threadIdx.x;

    float v[16];
    float m = __int_as_float(0xff800000);
#pragma unroll
    for (int i = 0; i < 16; i++) {
        v[i] = p[tid + i * 256];
        m = fmaxf(m, v[i]);
    }

    __shared__ float red[256];
    red[tid] = m;
    __syncthreads();
#pragma unroll
    for (int s = 128; s > 0; s >>= 1) {
        if (tid < s) red[tid] = fmaxf(red[tid], red[tid + s]);
        __syncthreads();
    }
    m = red[0];
    __syncthreads();

    float sum = 0.0f;
#pragma unroll
    for (int i = 0; i < 16; i++) {
        v[i] = __expf(v[i] - m);
        sum += v[i];
    }
    red[tid] = sum;
    __syncthreads();
#pragma unroll
    for (int s = 128; s > 0; s >>= 1) {
        if (tid < s) red[tid] += red[tid + s];
        __syncthreads();
    }
    const float inv = 1.0f / red[0];
#pragma unroll
    for (int i = 0; i < 16; i++) p[tid + i * 256] = v[i] * inv;
}

// ---------------------------------------------------------------------------
// Host-side GEMM dispatch helper
// ---------------------------------------------------------------------------
static void run_gemm(const float* A, const float* Bm, float* C,
                     int M, int N, int K,
                     long long sA, long long sB, long long sC, int batch,
                     bool transB,
                     const float* biasN, const float* biasM, float scale,
                     const int* mask, long long sMask)
{
    dim3 grid(N / BN, M / BM, batch), block(256);
    if (transB)
        sgemm_kernel<true><<<grid, block>>>(A, Bm, C, M, N, K, sA, sB, sC,
                                            biasN, biasM, scale, mask, sMask);
    else
        sgemm_kernel<false><<<grid, block>>>(A, Bm, C, M, N, K, sA, sB, sC,
                                             biasN, biasM, scale, mask, sMask);
}

// ---------------------------------------------------------------------------
// kernel_launch
// Inputs (metadata order = setup_inputs dict order):
//  0 queries [8,4096,512] f32      1 keys [8,4096,512] f32
//  2 values  [8,4096,512] f32      3 attention_mask [8,1024,4096] int32(bool)
//  4 Wq [512,512]   5 bq [512]     6 Wk [512,512]   7 bk [512]
//  8 Wv [512,512]   9 bv [512]    10 Wo [512,512]  11 bo [512]
// 12 Wd [1024,4096] 13 bd [1024]
// Output: [8,1024,512] f32
// ---------------------------------------------------------------------------
extern "C" void kernel_launch(void* const* d_in, const int* in_sizes, int n_in,
                              void* d_out, int out_size)
{
    (void)in_sizes; (void)n_in; (void)out_size;

    const float* queries = (const float*)d_in[0];
    const float* keys    = (const float*)d_in[1];
    const float* values  = (const float*)d_in[2];
    const int*   mask    = (const int*)d_in[3];
    const float* Wq = (const float*)d_in[4];
    const float* bq = (const float*)d_in[5];
    const float* Wk = (const float*)d_in[6];
    const float* bk = (const float*)d_in[7];
    const float* Wv = (const float*)d_in[8];
    const float* bv = (const float*)d_in[9];
    const float* Wo = (const float*)d_in[10];
    const float* bo = (const float*)d_in[11];
    const float* Wd = (const float*)d_in[12];
    const float* bd = (const float*)d_in[13];
    float* out = (float*)d_out;

    float *p_qds, *p_q, *p_k, *p_v, *p_s, *p_att;
    cudaGetSymbolAddress((void**)&p_qds, g_qds);
    cudaGetSymbolAddress((void**)&p_q,   g_q);
    cudaGetSymbolAddress((void**)&p_k,   g_k);
    cudaGetSymbolAddress((void**)&p_v,   g_v);
    cudaGetSymbolAddress((void**)&p_s,   g_s);
    cudaGetSymbolAddress((void**)&p_att, g_att);

    // 1. Downsample: qds[b,qa,d] = sum_qb Wd[qa,qb] * queries[b,qb,d] + bd[qa]
    //    (NN GEMM, A = Wd shared across batch, biasM = bd)
    run_gemm(Wd, queries, p_qds,
             QAFT, DMODEL, QBEF,
             0, (long long)QBEF * DMODEL, (long long)QAFT * DMODEL, BATCH,
             false, nullptr, bd, 1.0f, nullptr, 0);

    // 2. Q projection: q = qds @ Wq^T + bq   (flatten batch into M)
    run_gemm(p_qds, Wq, p_q,
             BATCH * QAFT, DMODEL, DMODEL,
             0, 0, 0, 1,
             true, bq, nullptr, 1.0f, nullptr, 0);

    // 3. K projection
    run_gemm(keys, Wk, p_k,
             BATCH * NKEYS, DMODEL, DMODEL,
             0, 0, 0, 1,
             true, bk, nullptr, 1.0f, nullptr, 0);

    // 4. V projection
    run_gemm(values, Wv, p_v,
             BATCH * NKEYS, DMODEL, DMODEL,
             0, 0, 0, 1,
             true, bv, nullptr, 1.0f, nullptr, 0);

    // 5. Scores: s[b,q,k] = (q . k)/sqrt(512), masked -> -inf
    run_gemm(p_q, p_k, p_s,
             QAFT, NKEYS, DMODEL,
             (long long)QAFT * DMODEL, (long long)NKEYS * DMODEL,
             (long long)QAFT * NKEYS, BATCH,
             true, nullptr, nullptr, 0.044194173824159216f,
             mask, (long long)QAFT * NKEYS);

    // 6. Softmax over keys (in place)
    softmax_kernel<<<BATCH * QAFT, 256>>>(p_s);

    // 7. PV: att[b,q,d] = sum_k s[b,q,k] * v[b,k,d]   (NN)
    run_gemm(p_s, p_v, p_att,
             QAFT, DMODEL, NKEYS,
             (long long)QAFT * NKEYS, (long long)NKEYS * DMODEL,
             (long long)QAFT * DMODEL, BATCH,
             false, nullptr, nullptr, 1.0f, nullptr, 0);

    // 8. Output projection -> d_out
    run_gemm(p_att, Wo, out,
             BATCH * QAFT, DMODEL, DMODEL,
             0, 0, 0, 1,
             true, bo, nullptr, 1.0f, nullptr, 0);
}

// round 4
// speedup vs baseline: 2.1556x; 2.1556x over previous
#include <cuda_runtime.h>
#include <cuda_bf16.h>
#include <cstdint>

// ---------------------------------------------------------------------------
// Problem dims
// ---------------------------------------------------------------------------
#define BATCH  8
#define DMODEL 512
#define QBEF   4096
#define QAFT   1024
#define NKEYS  4096

// ---------------------------------------------------------------------------
// Scratch: bf16 hi/lo split arrays + fp32 scores
// ---------------------------------------------------------------------------
#define N_QKV  (BATCH * QBEF * DMODEL)     // 16,777,216
#define N_QDS  (BATCH * QAFT * DMODEL)     // 4,194,304
#define N_S    (BATCH * QAFT * NKEYS)      // 33,554,432
#define N_WD   (QAFT * QBEF)               // 4,194,304
#define N_W    (DMODEL * DMODEL)           // 262,144

__device__ __align__(16) __nv_bfloat16 g_qih[N_QKV], g_qil[N_QKV];   // split queries
__device__ __align__(16) __nv_bfloat16 g_kih[N_QKV], g_kil[N_QKV];   // split keys
__device__ __align__(16) __nv_bfloat16 g_vih[N_QKV], g_vil[N_QKV];   // split values
__device__ __align__(16) __nv_bfloat16 g_wdh[N_WD],  g_wdl[N_WD];
__device__ __align__(16) __nv_bfloat16 g_wqh[N_W],   g_wql[N_W];
__device__ __align__(16) __nv_bfloat16 g_wkh[N_W],   g_wkl[N_W];
__device__ __align__(16) __nv_bfloat16 g_wvh[N_W],   g_wvl[N_W];
__device__ __align__(16) __nv_bfloat16 g_woh[N_W],   g_wol[N_W];
__device__ __align__(16) __nv_bfloat16 g_qdsh[N_QDS], g_qdsl[N_QDS];
__device__ __align__(16) __nv_bfloat16 g_qh[N_QDS],   g_ql[N_QDS];
__device__ __align__(16) __nv_bfloat16 g_kh[N_QKV],   g_kl[N_QKV];
__device__ __align__(16) __nv_bfloat16 g_vh[N_QKV],   g_vl[N_QKV];
__device__ __align__(16) float         g_s[N_S];                      // fp32 scores
__device__ __align__(16) __nv_bfloat16 g_ph[N_S],     g_pl[N_S];      // split softmax P
__device__ __align__(16) __nv_bfloat16 g_atth[N_QDS], g_attl[N_QDS];

// ---------------------------------------------------------------------------
// PTX helpers
// ---------------------------------------------------------------------------
__device__ __forceinline__ void cpasync16(uint32_t dst, const void* src) {
    asm volatile("cp.async.cg.shared.global [%0], [%1], 16;\n" :: "r"(dst), "l"(src));
}
__device__ __forceinline__ void cp_commit() { asm volatile("cp.async.commit_group;\n"); }
__device__ __forceinline__ void cp_wait1()  { asm volatile("cp.async.wait_group 1;\n"); }

__device__ __forceinline__ void ldsm4(uint32_t* r, uint32_t a) {
    asm volatile("ldmatrix.sync.aligned.m8n8.x4.shared.b16 {%0,%1,%2,%3}, [%4];"
        : "=r"(r[0]), "=r"(r[1]), "=r"(r[2]), "=r"(r[3]) : "r"(a));
}
__device__ __forceinline__ void ldsm4t(uint32_t* r, uint32_t a) {
    asm volatile("ldmatrix.sync.aligned.m8n8.x4.trans.shared.b16 {%0,%1,%2,%3}, [%4];"
        : "=r"(r[0]), "=r"(r[1]), "=r"(r[2]), "=r"(r[3]) : "r"(a));
}
__device__ __forceinline__ void mma16816(float* c, const uint32_t* a, const uint32_t* b) {
    asm volatile(
        "mma.sync.aligned.m16n8k16.row.col.f32.bf16.bf16.f32 "
        "{%0,%1,%2,%3}, {%4,%5,%6,%7}, {%8,%9}, {%0,%1,%2,%3};"
        : "+f"(c[0]), "+f"(c[1]), "+f"(c[2]), "+f"(c[3])
        : "r"(a[0]), "r"(a[1]), "r"(a[2]), "r"(a[3]), "r"(b[0]), "r"(b[1]));
}

// ---------------------------------------------------------------------------
// bf16x3 GEMM.  C = scale * (A @ op(B)) (+biasM)(+biasN) (mask -> -inf)
// A = Ah+Al [M,K] row-major bf16 pairs.  op(B)=B^T if TRANSB (B is [N,K]),
// else B is [K,N].  Output: fp32 (Cf) OR split bf16 (Ch,Cl).
// Tiles: BM=128, BN=64, BK=32. 256 threads = 8 warps (4 m x 2 n), warp 32x32.
// ---------------------------------------------------------------------------
#define STAGES 3
#define STAGE_BYTES 30720     // Ah 10240 + Al 10240 + Bh 5120 + Bl 5120
#define SMEM_TOTAL (STAGES * STAGE_BYTES)
#define LDA 40                // 32 + 8 pad (bf16 elems)
#define LDB_NT 40
#define LDB_NN 72             // 64 + 8 pad

template <bool TRANSB>
__global__ __launch_bounds__(256)
void gemm3_kernel(const __nv_bfloat16* __restrict__ Ahg, const __nv_bfloat16* __restrict__ Alg,
                  const __nv_bfloat16* __restrict__ Bhg, const __nv_bfloat16* __restrict__ Blg,
                  float* __restrict__ Cf, __nv_bfloat16* __restrict__ Ch, __nv_bfloat16* __restrict__ Cl,
                  int M, int N, int K,
                  long long sA, long long sB, long long sC,
                  const float* __restrict__ biasN, const float* __restrict__ biasM,
                  float scale, const int* __restrict__ mask, long long sMask)
{
    extern __shared__ __align__(16) char smem_buf[];
    const int tid  = threadIdx.x;
    const int lane = tid & 31;
    const int warp = tid >> 5;
    const int warpM = warp >> 1;      // 0..3
    const int warpN = warp & 1;       // 0..1
    const int bz = blockIdx.z;
    const int rowBase = blockIdx.y * 128;
    const int colBase = blockIdx.x * 64;

    const __nv_bfloat16* Ah = Ahg + bz * sA;
    const __nv_bfloat16* Al = Alg + bz * sA;
    const __nv_bfloat16* Bh = Bhg + bz * sB;
    const __nv_bfloat16* Bl = Blg + bz * sB;

    const uint32_t smb = (uint32_t)__cvta_generic_to_shared(smem_buf);

    auto load_stage = [&](int kt, int s) {
        const uint32_t base = smb + s * STAGE_BYTES;
#pragma unroll
        for (int i = 0; i < 2; i++) {
            int idx = tid + i * 256;
            int row = idx >> 2, c8 = (idx & 3) * 8;
            size_t go = (size_t)(rowBase + row) * K + kt * 32 + c8;
            uint32_t d = base + (uint32_t)(row * LDA + c8) * 2;
            cpasync16(d,         Ah + go);
            cpasync16(d + 10240, Al + go);
        }
        if (TRANSB) {
            int n = tid >> 2, c8 = (tid & 3) * 8;
            size_t go = (size_t)(colBase + n) * K + kt * 32 + c8;
            uint32_t d = base + 20480 + (uint32_t)(n * LDB_NT + c8) * 2;
            cpasync16(d,        Bh + go);
            cpasync16(d + 5120, Bl + go);
        } else {
            int k = tid >> 3, c8 = (tid & 7) * 8;
            size_t go = (size_t)(kt * 32 + k) * N + colBase + c8;
            uint32_t d = base + 20480 + (uint32_t)(k * LDB_NN + c8) * 2;
            cpasync16(d,        Bh + go);
            cpasync16(d + 5120, Bl + go);
        }
    };

    // ldmatrix per-thread address components
    const int a_row = warpM * 32 + (lane & 15);
    const int a_col = ((lane >> 4) << 3);
    const uint32_t a_off = (uint32_t)(a_row * LDA + a_col) * 2;

    uint32_t b_off;
    if (TRANSB) {
        int b_n = warpN * 32 + (lane & 7) + ((lane >> 4) << 3);
        int b_k = ((lane >> 3) & 1) * 8;
        b_off = (uint32_t)(b_n * LDB_NT + b_k) * 2;
    } else {
        int b_k = lane & 15;
        int b_n = warpN * 32 + ((lane >> 4) << 3);
        b_off = (uint32_t)(b_k * LDB_NN + b_n) * 2;
    }

    float acc[2][4][4];
#pragma unroll
    for (int mt = 0; mt < 2; mt++)
#pragma unroll
        for (int nt = 0; nt < 4; nt++)
#pragma unroll
            for (int i = 0; i < 4; i++) acc[mt][nt][i] = 0.0f;

    const int nkt = K / 32;

    load_stage(0, 0); cp_commit();
    load_stage(1, 1); cp_commit();

    for (int kt = 0; kt < nkt; kt++) {
        cp_wait1();
        __syncthreads();

        int ls = kt + STAGES - 1;
        if (ls < nkt) load_stage(ls, ls % STAGES);
        cp_commit();

        const uint32_t sb = smb + (kt % STAGES) * STAGE_BYTES;
#pragma unroll
        for (int kk = 0; kk < 2; kk++) {
            uint32_t ah[2][4], al[2][4], bh[2][4], bl[2][4];
#pragma unroll
            for (int mt = 0; mt < 2; mt++) {
                uint32_t ao = sb + a_off + (uint32_t)(mt * 16 * LDA + kk * 16) * 2;
                ldsm4(ah[mt], ao);
                ldsm4(al[mt], ao + 10240);
            }
#pragma unroll
            for (int g4 = 0; g4 < 2; g4++) {
                if (TRANSB) {
                    uint32_t bo = sb + 20480 + b_off + (uint32_t)(g4 * 16 * LDB_NT + kk * 16) * 2;
                    ldsm4(bh[g4], bo);
                    ldsm4(bl[g4], bo + 5120);
                } else {
                    uint32_t bo = sb + 20480 + b_off + (uint32_t)(kk * 16 * LDB_NN + g4 * 16) * 2;
                    ldsm4t(bh[g4], bo);
                    ldsm4t(bl[g4], bo + 5120);
                }
            }
#pragma unroll
            for (int mt = 0; mt < 2; mt++) {
#pragma unroll
                for (int nt = 0; nt < 4; nt++) {
                    const int g4 = nt >> 1, hf = (nt & 1) * 2;
                    uint32_t bH[2] = { bh[g4][hf], bh[g4][hf + 1] };
                    uint32_t bL[2] = { bl[g4][hf], bl[g4][hf + 1] };
                    mma16816(acc[mt][nt], ah[mt], bH);
                    mma16816(acc[mt][nt], ah[mt], bL);
                    mma16816(acc[mt][nt], al[mt], bH);
                }
            }
        }
        __syncthreads();
    }

    // Epilogue
    const int g = lane >> 2, t = lane & 3;
    float* CfB = Cf ? (Cf + bz * sC) : nullptr;
    __nv_bfloat16* ChB = Ch ? (Ch + bz * sC) : nullptr;
    __nv_bfloat16* ClB = Cl ? (Cl + bz * sC) : nullptr;
    const int* maskB = mask ? (mask + bz * sMask) : nullptr;

#pragma unroll
    for (int mt = 0; mt < 2; mt++) {
#pragma unroll
        for (int nt = 0; nt < 4; nt++) {
            const int r0 = rowBase + warpM * 32 + mt * 16 + g;
            const int r1 = r0 + 8;
            const int cc = colBase + warpN * 32 + nt * 8 + 2 * t;
            float v00 = acc[mt][nt][0] * scale;
            float v01 = acc[mt][nt][1] * scale;
            float v10 = acc[mt][nt][2] * scale;
            float v11 = acc[mt][nt][3] * scale;
            if (biasM) {
                float b0 = biasM[r0], b1 = biasM[r1];
                v00 += b0; v01 += b0; v10 += b1; v11 += b1;
            }
            if (biasN) {
                float b0 = biasN[cc], b1 = biasN[cc + 1];
                v00 += b0; v01 += b1; v10 += b0; v11 += b1;
            }
            if (maskB) {
                const float NINF = __int_as_float(0xff800000);
                if (maskB[(long long)r0 * N + cc])     v00 = NINF;
                if (maskB[(long long)r0 * N + cc + 1]) v01 = NINF;
                if (maskB[(long long)r1 * N + cc])     v10 = NINF;
                if (maskB[(long long)r1 * N + cc + 1]) v11 = NINF;
            }
            if (CfB) {
                float2 f0 = make_float2(v00, v01);
                float2 f1 = make_float2(v10, v11);
                *(float2*)(CfB + (long long)r0 * N + cc) = f0;
                *(float2*)(CfB + (long long)r1 * N + cc) = f1;
            } else {
                __nv_bfloat16 h00 = __float2bfloat16_rn(v00);
                __nv_bfloat16 h01 = __float2bfloat16_rn(v01);
                __nv_bfloat16 h10 = __float2bfloat16_rn(v10);
                __nv_bfloat16 h11 = __float2bfloat16_rn(v11);
                __nv_bfloat162 H0; H0.x = h00; H0.y = h01;
                __nv_bfloat162 H1; H1.x = h10; H1.y = h11;
                __nv_bfloat162 L0; L0.x = __float2bfloat16_rn(v00 - __bfloat162float(h00));
                L0.y = __float2bfloat16_rn(v01 - __bfloat162float(h01));
                __nv_bfloat162 L1; L1.x = __float2bfloat16_rn(v10 - __bfloat162float(h10));
                L1.y = __float2bfloat16_rn(v11 - __bfloat162float(h11));
                *(__nv_bfloat162*)(ChB + (long long)r0 * N + cc) = H0;
                *(__nv_bfloat162*)(ChB + (long long)r1 * N + cc) = H1;
                *(__nv_bfloat162*)(ClB + (long long)r0 * N + cc) = L0;
                *(__nv_bfloat162*)(ClB + (long long)r1 * N + cc) = L1;
            }
        }
    }
}

// ---------------------------------------------------------------------------
// fp32 -> bf16 hi/lo split (elementwise, vectorized x4)
// ---------------------------------------------------------------------------
__global__ __launch_bounds__(256)
void split_kernel(const float* __restrict__ src,
                  __nv_bfloat16* __restrict__ h, __nv_bfloat16* __restrict__ l,
                  long long n)
{
    long long i = ((long long)blockIdx.x * 256 + threadIdx.x) * 4;
    if (i >= n) return;
    float4 v = *(const float4*)(src + i);
    __nv_bfloat16 h0 = __float2bfloat16_rn(v.x);
    __nv_bfloat16 h1 = __float2bfloat16_rn(v.y);
    __nv_bfloat16 h2 = __float2bfloat16_rn(v.z);
    __nv_bfloat16 h3 = __float2bfloat16_rn(v.w);
    __nv_bfloat162 H0; H0.x = h0; H0.y = h1;
    __nv_bfloat162 H1; H1.x = h2; H1.y = h3;
    __nv_bfloat162 L0, L1;
    L0.x = __float2bfloat16_rn(v.x - __bfloat162float(h0));
    L0.y = __float2bfloat16_rn(v.y - __bfloat162float(h1));
    L1.x = __float2bfloat16_rn(v.z - __bfloat162float(h2));
    L1.y = __float2bfloat16_rn(v.w - __bfloat162float(h3));
    *(__nv_bfloat162*)(h + i)     = H0;
    *(__nv_bfloat162*)(h + i + 2) = H1;
    *(__nv_bfloat162*)(l + i)     = L0;
    *(__nv_bfloat162*)(l + i + 2) = L1;
}

// ---------------------------------------------------------------------------
// Row softmax over NKEYS, fp32 in -> split bf16 out. One block per row.
// ---------------------------------------------------------------------------
__global__ __launch_bounds__(256)
void softmax_split_kernel(const float* __restrict__ S,
                          __nv_bfloat16* __restrict__ Ph, __nv_bfloat16* __restrict__ Pl)
{
    const float* p = S + (long long)blockIdx.x * NKEYS;
    __nv_bfloat16* ph = Ph + (long long)blockIdx.x * NKEYS;
    __nv_bfloat16* pl = Pl + (long long)blockIdx.x * NKEYS;
    const int tid = threadIdx.x;

    float v[16];
    float m = __int_as_float(0xff800000);
#pragma unroll
    for (int i = 0; i < 16; i++) { v[i] = p[tid + i * 256]; m = fmaxf(m, v[i]); }

    __shared__ float red[256];
    red[tid] = m; __syncthreads();
#pragma unroll
    for (int s = 128; s > 0; s >>= 1) {
        if (tid < s) red[tid] = fmaxf(red[tid], red[tid + s]);
        __syncthreads();
    }
    m = red[0]; __syncthreads();

    float sum = 0.0f;
#pragma unroll
    for (int i = 0; i < 16; i++) { v[i] = __expf(v[i] - m); sum += v[i]; }
    red[tid] = sum; __syncthreads();
#pragma unroll
    for (int s = 128; s > 0; s >>= 1) {
        if (tid < s) red[tid] += red[tid + s];
        __syncthreads();
    }
    const float inv = 1.0f / red[0];
#pragma unroll
    for (int i = 0; i < 16; i++) {
        float pv = v[i] * inv;
        __nv_bfloat16 h = __float2bfloat16_rn(pv);
        ph[tid + i * 256] = h;
        pl[tid + i * 256] = __float2bfloat16_rn(pv - __bfloat162float(h));
    }
}

// ---------------------------------------------------------------------------
// Host dispatch
// ---------------------------------------------------------------------------
static void run_gemm3(const __nv_bfloat16* Ah, const __nv_bfloat16* Al,
                      const __nv_bfloat16* Bh, const __nv_bfloat16* Bl,
                      float* Cf, __nv_bfloat16* Ch, __nv_bfloat16* Cl,
                      int M, int N, int K,
                      long long sA, long long sB, long long sC, int batch,
                      bool transB,
                      const float* biasN, const float* biasM, float scale,
                      const int* mask, long long sMask)
{
    dim3 grid(N / 64, M / 128, batch), block(256);
    if (transB)
        gemm3_kernel<true><<<grid, block, SMEM_TOTAL>>>(Ah, Al, Bh, Bl, Cf, Ch, Cl,
            M, N, K, sA, sB, sC, biasN, biasM, scale, mask, sMask);
    else
        gemm3_kernel<false><<<grid, block, SMEM_TOTAL>>>(Ah, Al, Bh, Bl, Cf, Ch, Cl,
            M, N, K, sA, sB, sC, biasN, biasM, scale, mask, sMask);
}

static void run_split(const float* src, __nv_bfloat16* h, __nv_bfloat16* l, long long n)
{
    split_kernel<<<(unsigned)((n / 4 + 255) / 256), 256>>>(src, h, l, n);
}

extern "C" void kernel_launch(void* const* d_in, const int* in_sizes, int n_in,
                              void* d_out, int out_size)
{
    (void)in_sizes; (void)n_in; (void)out_size;

    const float* queries = (const float*)d_in[0];
    const float* keys    = (const float*)d_in[1];
    const float* values  = (const float*)d_in[2];
    const int*   mask    = (const int*)d_in[3];
    const float* bq = (const float*)d_in[5];
    const float* bk = (const float*)d_in[7];
    const float* bv = (const float*)d_in[9];
    const float* bo = (const float*)d_in[11];
    const float* Wq = (const float*)d_in[4];
    const float* Wk = (const float*)d_in[6];
    const float* Wv = (const float*)d_in[8];
    const float* Wo = (const float*)d_in[10];
    const float* Wd = (const float*)d_in[12];
    const float* bd = (const float*)d_in[13];
    float* out = (float*)d_out;

    cudaFuncSetAttribute(gemm3_kernel<true>,  cudaFuncAttributeMaxDynamicSharedMemorySize, SMEM_TOTAL);
    cudaFuncSetAttribute(gemm3_kernel<false>, cudaFuncAttributeMaxDynamicSharedMemorySize, SMEM_TOTAL);

    __nv_bfloat16 *qih,*qil,*kih,*kil,*vih,*vil,*wdh,*wdl,*wqh,*wql,*wkh,*wkl,*wvh,*wvl,*woh,*wol;
    __nv_bfloat16 *qdsh,*qdsl,*qh,*ql,*kh,*kl,*vh,*vl,*ph,*pl,*atth,*attl;
    float *sS;
    cudaGetSymbolAddress((void**)&qih, g_qih);   cudaGetSymbolAddress((void**)&qil, g_qil);
    cudaGetSymbolAddress((void**)&kih, g_kih);   cudaGetSymbolAddress((void**)&kil, g_kil);
    cudaGetSymbolAddress((void**)&vih, g_vih);   cudaGetSymbolAddress((void**)&vil, g_vil);
    cudaGetSymbolAddress((void**)&wdh, g_wdh);   cudaGetSymbolAddress((void**)&wdl, g_wdl);
    cudaGetSymbolAddress((void**)&wqh, g_wqh);   cudaGetSymbolAddress((void**)&wql, g_wql);
    cudaGetSymbolAddress((void**)&wkh, g_wkh);   cudaGetSymbolAddress((void**)&wkl, g_wkl);
    cudaGetSymbolAddress((void**)&wvh, g_wvh);   cudaGetSymbolAddress((void**)&wvl, g_wvl);
    cudaGetSymbolAddress((void**)&woh, g_woh);   cudaGetSymbolAddress((void**)&wol, g_wol);
    cudaGetSymbolAddress((void**)&qdsh, g_qdsh); cudaGetSymbolAddress((void**)&qdsl, g_qdsl);
    cudaGetSymbolAddress((void**)&qh, g_qh);     cudaGetSymbolAddress((void**)&ql, g_ql);
    cudaGetSymbolAddress((void**)&kh, g_kh);     cudaGetSymbolAddress((void**)&kl, g_kl);
    cudaGetSymbolAddress((void**)&vh, g_vh);     cudaGetSymbolAddress((void**)&vl, g_vl);
    cudaGetSymbolAddress((void**)&ph, g_ph);     cudaGetSymbolAddress((void**)&pl, g_pl);
    cudaGetSymbolAddress((void**)&atth, g_atth); cudaGetSymbolAddress((void**)&attl, g_attl);
    cudaGetSymbolAddress((void**)&sS, g_s);

    // --- split fp32 inputs into bf16 hi/lo ---
    run_split(queries, qih, qil, N_QKV);
    run_split(keys,    kih, kil, N_QKV);
    run_split(values,  vih, vil, N_QKV);
    run_split(Wd, wdh, wdl, N_WD);
    run_split(Wq, wqh, wql, N_W);
    run_split(Wk, wkh, wkl, N_W);
    run_split(Wv, wvh, wvl, N_W);
    run_split(Wo, woh, wol, N_W);

    // 1. Downsample (NN): qds[b] = Wd @ queries[b] + bd (row bias)
    run_gemm3(wdh, wdl, qih, qil, nullptr, qdsh, qdsl,
              QAFT, DMODEL, QBEF,
              0, (long long)QBEF * DMODEL, (long long)QAFT * DMODEL, BATCH,
              false, nullptr, bd, 1.0f, nullptr, 0);

    // 2. Q projection (NT, flattened batch): q = qds @ Wq^T + bq
    run_gemm3(qdsh, qdsl, wqh, wql, nullptr, qh, ql,
              BATCH * QAFT, DMODEL, DMODEL, 0, 0, 0, 1,
              true, bq, nullptr, 1.0f, nullptr, 0);

    // 3. K projection
    run_gemm3(kih, kil, wkh, wkl, nullptr, kh, kl,
              BATCH * NKEYS, DMODEL, DMODEL, 0, 0, 0, 1,
              true, bk, nullptr, 1.0f, nullptr, 0);

    // 4. V projection
    run_gemm3(vih, vil, wvh, wvl, nullptr, vh, vl,
              BATCH * NKEYS, DMODEL, DMODEL, 0, 0, 0, 1,
              true, bv, nullptr, 1.0f, nullptr, 0);

    // 5. Scores (NT): s = (q @ k^T)/sqrt(512), masked -> -inf, fp32 out
    run_gemm3(qh, ql, kh, kl, sS, nullptr, nullptr,
              QAFT, NKEYS, DMODEL,
              (long long)QAFT * DMODEL, (long long)NKEYS * DMODEL,
              (long long)QAFT * NKEYS, BATCH,
              true, nullptr, nullptr, 0.044194173824159216f,
              mask, (long long)QAFT * NKEYS);

    // 6. Softmax -> split P
    softmax_split_kernel<<<BATCH * QAFT, 256>>>(sS, ph, pl);

    // 7. PV (NN): att[b] = P[b] @ v[b]
    run_gemm3(ph, pl, vh, vl, nullptr, atth, attl,
              QAFT, DMODEL, NKEYS,
              (long long)QAFT * NKEYS, (long long)NKEYS * DMODEL,
              (long long)QAFT * DMODEL, BATCH,
              false, nullptr, nullptr, 1.0f, nullptr, 0);

    // 8. Output projection (NT) -> fp32 d_out
    run_gemm3(atth, attl, woh, wol, out, nullptr, nullptr,
              BATCH * QAFT, DMODEL, DMODEL, 0, 0, 0, 1,
              true, bo, nullptr, 1.0f, nullptr, 0);
}

// round 5
// speedup vs baseline: 2.1904x; 1.0161x over previous
#include <cuda_runtime.h>
#include <cuda_bf16.h>
#include <cstdint>

// ---------------------------------------------------------------------------
// Problem dims
// ---------------------------------------------------------------------------
#define BATCH  8
#define DMODEL 512
#define QBEF   4096
#define QAFT   1024
#define NKEYS  4096

#define N_QKV  (BATCH * QBEF * DMODEL)
#define N_QDS  (BATCH * QAFT * DMODEL)
#define N_S    (BATCH * QAFT * NKEYS)
#define N_WD   (QAFT * QBEF)
#define N_W    (DMODEL * DMODEL)

__device__ __align__(16) __nv_bfloat16 g_qih[N_QKV], g_qil[N_QKV];
__device__ __align__(16) __nv_bfloat16 g_kih[N_QKV], g_kil[N_QKV];
__device__ __align__(16) __nv_bfloat16 g_vih[N_QKV], g_vil[N_QKV];
__device__ __align__(16) __nv_bfloat16 g_wdh[N_WD],  g_wdl[N_WD];
__device__ __align__(16) __nv_bfloat16 g_wqh[N_W],   g_wql[N_W];
__device__ __align__(16) __nv_bfloat16 g_wkh[N_W],   g_wkl[N_W];
__device__ __align__(16) __nv_bfloat16 g_wvh[N_W],   g_wvl[N_W];
__device__ __align__(16) __nv_bfloat16 g_woh[N_W],   g_wol[N_W];
__device__ __align__(16) __nv_bfloat16 g_qdsh[N_QDS], g_qdsl[N_QDS];
__device__ __align__(16) __nv_bfloat16 g_qh[N_QDS],   g_ql[N_QDS];
__device__ __align__(16) __nv_bfloat16 g_kh[N_QKV],   g_kl[N_QKV];
__device__ __align__(16) __nv_bfloat16 g_vh[N_QKV],   g_vl[N_QKV];
__device__ __align__(16) float         g_s[N_S];
__device__ __align__(16) __nv_bfloat16 g_ph[N_S],     g_pl[N_S];
__device__ __align__(16) __nv_bfloat16 g_atth[N_QDS], g_attl[N_QDS];

// ---------------------------------------------------------------------------
// PTX helpers
// ---------------------------------------------------------------------------
__device__ __forceinline__ void cpasync16(uint32_t dst, const void* src) {
    asm volatile("cp.async.cg.shared.global [%0], [%1], 16;\n" :: "r"(dst), "l"(src));
}
__device__ __forceinline__ void cp_commit() { asm volatile("cp.async.commit_group;\n"); }
__device__ __forceinline__ void cp_wait1()  { asm volatile("cp.async.wait_group 1;\n"); }

__device__ __forceinline__ void ldsm4(uint32_t* r, uint32_t a) {
    asm volatile("ldmatrix.sync.aligned.m8n8.x4.shared.b16 {%0,%1,%2,%3}, [%4];"
        : "=r"(r[0]), "=r"(r[1]), "=r"(r[2]), "=r"(r[3]) : "r"(a));
}
__device__ __forceinline__ void ldsm4t(uint32_t* r, uint32_t a) {
    asm volatile("ldmatrix.sync.aligned.m8n8.x4.trans.shared.b16 {%0,%1,%2,%3}, [%4];"
        : "=r"(r[0]), "=r"(r[1]), "=r"(r[2]), "=r"(r[3]) : "r"(a));
}
__device__ __forceinline__ void mma16816(float* c, const uint32_t* a, const uint32_t* b) {
    asm volatile(
        "mma.sync.aligned.m16n8k16.row.col.f32.bf16.bf16.f32 "
        "{%0,%1,%2,%3}, {%4,%5,%6,%7}, {%8,%9}, {%0,%1,%2,%3};"
        : "+f"(c[0]), "+f"(c[1]), "+f"(c[2]), "+f"(c[3])
        : "r"(a[0]), "r"(a[1]), "r"(a[2]), "r"(a[3]), "r"(b[0]), "r"(b[1]));
}

// ---------------------------------------------------------------------------
// bf16x3 GEMM, tile 128x128, BK=32, 8 warps (4m x 2n), warp tile 32x64.
// A = Ah+Al [M,K] row-major.  op(B)=B^T if TRANSB (B:[N,K]) else B:[K,N].
// Output: fp32 (Cf) or split bf16 (Ch,Cl). Optional biasM/biasN/scale/mask.
// ---------------------------------------------------------------------------
#define STAGES 3
#define LDA 40
#define LDB_NT 40
#define LDB_NN 136

template <bool TRANSB>
__global__ __launch_bounds__(256, 1)
void gemm3_kernel(const __nv_bfloat16* __restrict__ Ahg, const __nv_bfloat16* __restrict__ Alg,
                  const __nv_bfloat16* __restrict__ Bhg, const __nv_bfloat16* __restrict__ Blg,
                  float* __restrict__ Cf, __nv_bfloat16* __restrict__ Ch, __nv_bfloat16* __restrict__ Cl,
                  int M, int N, int K,
                  long long sA, long long sB, long long sC,
                  const float* __restrict__ biasN, const float* __restrict__ biasM,
                  float scale, const int* __restrict__ mask, long long sMask)
{
    // Smem layout per stage: [Ah 10240][Al 10240][Bh BHALF][Bl BHALF]
    constexpr uint32_t BHALF = TRANSB ? (128u * LDB_NT * 2u) : (32u * LDB_NN * 2u);
    constexpr uint32_t STAGE_BYTES = 20480u + 2u * BHALF;

    extern __shared__ __align__(16) char smem_buf[];
    const int tid  = threadIdx.x;
    const int lane = tid & 31;
    const int warp = tid >> 5;
    const int warpM = warp >> 1;      // 0..3 (32 rows each)
    const int warpN = warp & 1;       // 0..1 (64 cols each)
    const int bz = blockIdx.z;
    const int rowBase = blockIdx.y * 128;
    const int colBase = blockIdx.x * 128;

    const __nv_bfloat16* Ah = Ahg + bz * sA;
    const __nv_bfloat16* Al = Alg + bz * sA;
    const __nv_bfloat16* Bh = Bhg + bz * sB;
    const __nv_bfloat16* Bl = Blg + bz * sB;

    const uint32_t smb = (uint32_t)__cvta_generic_to_shared(smem_buf);

    auto load_stage = [&](int kt, int s) {
        const uint32_t base = smb + s * STAGE_BYTES;
#pragma unroll
        for (int i = 0; i < 2; i++) {
            int idx = tid + i * 256;
            int row = idx >> 2, c8 = (idx & 3) * 8;
            size_t go = (size_t)(rowBase + row) * K + kt * 32 + c8;
            uint32_t d = base + (uint32_t)(row * LDA + c8) * 2;
            cpasync16(d,         Ah + go);
            cpasync16(d + 10240, Al + go);
        }
        if (TRANSB) {
#pragma unroll
            for (int i = 0; i < 2; i++) {
                int idx = tid + i * 256;
                int n = idx >> 2, c8 = (idx & 3) * 8;
                size_t go = (size_t)(colBase + n) * K + kt * 32 + c8;
                uint32_t d = base + 20480 + (uint32_t)(n * LDB_NT + c8) * 2;
                cpasync16(d,         Bh + go);
                cpasync16(d + BHALF, Bl + go);
            }
        } else {
#pragma unroll
            for (int i = 0; i < 2; i++) {
                int idx = tid + i * 256;
                int k = idx >> 4, c8 = (idx & 15) * 8;
                size_t go = (size_t)(kt * 32 + k) * N + colBase + c8;
                uint32_t d = base + 20480 + (uint32_t)(k * LDB_NN + c8) * 2;
                cpasync16(d,         Bh + go);
                cpasync16(d + BHALF, Bl + go);
            }
        }
    };

    // ldmatrix per-thread address components
    const int a_row = warpM * 32 + (lane & 15);
    const int a_col = ((lane >> 4) << 3);
    const uint32_t a_off = (uint32_t)(a_row * LDA + a_col) * 2;

    uint32_t b_off;
    if (TRANSB) {
        int b_n = warpN * 64 + (lane & 7) + ((lane >> 4) << 3);
        int b_k = ((lane >> 3) & 1) * 8;
        b_off = (uint32_t)(b_n * LDB_NT + b_k) * 2;
    } else {
        int b_k = lane & 15;
        int b_n = warpN * 64 + ((lane >> 4) << 3);
        b_off = (uint32_t)(b_k * LDB_NN + b_n) * 2;
    }

    float acc[2][8][4];
#pragma unroll
    for (int mt = 0; mt < 2; mt++)
#pragma unroll
        for (int nt = 0; nt < 8; nt++)
#pragma unroll
            for (int i = 0; i < 4; i++) acc[mt][nt][i] = 0.0f;

    const int nkt = K / 32;

    load_stage(0, 0); cp_commit();
    load_stage(1, 1); cp_commit();

    for (int kt = 0; kt < nkt; kt++) {
        cp_wait1();
        __syncthreads();

        int ls = kt + STAGES - 1;
        if (ls < nkt) load_stage(ls, ls % STAGES);
        cp_commit();

        const uint32_t sb = smb + (kt % STAGES) * STAGE_BYTES;
#pragma unroll
        for (int kk = 0; kk < 2; kk++) {
            uint32_t ah[2][4], al[2][4], bh[4][4], bl[4][4];
#pragma unroll
            for (int mt = 0; mt < 2; mt++) {
                uint32_t ao = sb + a_off + (uint32_t)(mt * 16 * LDA + kk * 16) * 2;
                ldsm4(ah[mt], ao);
                ldsm4(al[mt], ao + 10240);
            }
#pragma unroll
            for (int g4 = 0; g4 < 4; g4++) {
                if (TRANSB) {
                    uint32_t bo = sb + 20480 + b_off + (uint32_t)(g4 * 16 * LDB_NT + kk * 16) * 2;
                    ldsm4(bh[g4], bo);
                    ldsm4(bl[g4], bo + BHALF);
                } else {
                    uint32_t bo = sb + 20480 + b_off + (uint32_t)(kk * 16 * LDB_NN + g4 * 16) * 2;
                    ldsm4t(bh[g4], bo);
                    ldsm4t(bl[g4], bo + BHALF);
                }
            }
#pragma unroll
            for (int mt = 0; mt < 2; mt++) {
#pragma unroll
                for (int nt = 0; nt < 8; nt++) {
                    const int g4 = nt >> 1, hf = (nt & 1) * 2;
                    uint32_t bH[2] = { bh[g4][hf], bh[g4][hf + 1] };
                    uint32_t bL[2] = { bl[g4][hf], bl[g4][hf + 1] };
                    mma16816(acc[mt][nt], ah[mt], bH);
                    mma16816(acc[mt][nt], ah[mt], bL);
                    mma16816(acc[mt][nt], al[mt], bH);
                }
            }
        }
        __syncthreads();
    }

    // Epilogue
    const int g = lane >> 2, t = lane & 3;
    float* CfB = Cf ? (Cf + bz * sC) : nullptr;
    __nv_bfloat16* ChB = Ch ? (Ch + bz * sC) : nullptr;
    __nv_bfloat16* ClB = Cl ? (Cl + bz * sC) : nullptr;
    const int* maskB = mask ? (mask + bz * sMask) : nullptr;

#pragma unroll
    for (int mt = 0; mt < 2; mt++) {
#pragma unroll
        for (int nt = 0; nt < 8; nt++) {
            const int r0 = rowBase + warpM * 32 + mt * 16 + g;
            const int r1 = r0 + 8;
            const int cc = colBase + warpN * 64 + nt * 8 + 2 * t;
            float v00 = acc[mt][nt][0] * scale;
            float v01 = acc[mt][nt][1] * scale;
            float v10 = acc[mt][nt][2] * scale;
            float v11 = acc[mt][nt][3] * scale;
            if (biasM) {
                float b0 = biasM[r0], b1 = biasM[r1];
                v00 += b0; v01 += b0; v10 += b1; v11 += b1;
            }
            if (biasN) {
                float b0 = biasN[cc], b1 = biasN[cc + 1];
                v00 += b0; v01 += b1; v10 += b0; v11 += b1;
            }
            if (maskB) {
                const float NINF = __int_as_float(0xff800000);
                if (maskB[(long long)r0 * N + cc])     v00 = NINF;
                if (maskB[(long long)r0 * N + cc + 1]) v01 = NINF;
                if (maskB[(long long)r1 * N + cc])     v10 = NINF;
                if (maskB[(long long)r1 * N + cc + 1]) v11 = NINF;
            }
            if (CfB) {
                *(float2*)(CfB + (long long)r0 * N + cc) = make_float2(v00, v01);
                *(float2*)(CfB + (long long)r1 * N + cc) = make_float2(v10, v11);
            } else {
                __nv_bfloat16 h00 = __float2bfloat16_rn(v00);
                __nv_bfloat16 h01 = __float2bfloat16_rn(v01);
                __nv_bfloat16 h10 = __float2bfloat16_rn(v10);
                __nv_bfloat16 h11 = __float2bfloat16_rn(v11);
                __nv_bfloat162 H0; H0.x = h00; H0.y = h01;
                __nv_bfloat162 H1; H1.x = h10; H1.y = h11;
                __nv_bfloat162 L0, L1;
                L0.x = __float2bfloat16_rn(v00 - __bfloat162float(h00));
                L0.y = __float2bfloat16_rn(v01 - __bfloat162float(h01));
                L1.x = __float2bfloat16_rn(v10 - __bfloat162float(h10));
                L1.y = __float2bfloat16_rn(v11 - __bfloat162float(h11));
                *(__nv_bfloat162*)(ChB + (long long)r0 * N + cc) = H0;
                *(__nv_bfloat162*)(ChB + (long long)r1 * N + cc) = H1;
                *(__nv_bfloat162*)(ClB + (long long)r0 * N + cc) = L0;
                *(__nv_bfloat162*)(ClB + (long long)r1 * N + cc) = L1;
            }
        }
    }
}

// ---------------------------------------------------------------------------
// Fused splits: fp32 -> bf16 hi/lo
// ---------------------------------------------------------------------------
__device__ __forceinline__ void split4(const float* src, __nv_bfloat16* h,
                                       __nv_bfloat16* l, long long i)
{
    float4 v = *(const float4*)(src + i);
    __nv_bfloat16 h0 = __float2bfloat16_rn(v.x);
    __nv_bfloat16 h1 = __float2bfloat16_rn(v.y);
    __nv_bfloat16 h2 = __float2bfloat16_rn(v.z);
    __nv_bfloat16 h3 = __float2bfloat16_rn(v.w);
    __nv_bfloat162 H0; H0.x = h0; H0.y = h1;
    __nv_bfloat162 H1; H1.x = h2; H1.y = h3;
    __nv_bfloat162 L0, L1;
    L0.x = __float2bfloat16_rn(v.x - __bfloat162float(h0));
    L0.y = __float2bfloat16_rn(v.y - __bfloat162float(h1));
    L1.x = __float2bfloat16_rn(v.z - __bfloat162float(h2));
    L1.y = __float2bfloat16_rn(v.w - __bfloat162float(h3));
    *(__nv_bfloat162*)(h + i)     = H0;
    *(__nv_bfloat162*)(h + i + 2) = H1;
    *(__nv_bfloat162*)(l + i)     = L0;
    *(__nv_bfloat162*)(l + i + 2) = L1;
}

// q/k/v (same size) in one launch: blockIdx.y selects tensor
__global__ __launch_bounds__(256)
void split3_kernel(const float* __restrict__ s0, const float* __restrict__ s1,
                   const float* __restrict__ s2,
                   __nv_bfloat16* __restrict__ h0, __nv_bfloat16* __restrict__ l0,
                   __nv_bfloat16* __restrict__ h1, __nv_bfloat16* __restrict__ l1,
                   __nv_bfloat16* __restrict__ h2, __nv_bfloat16* __restrict__ l2)
{
    long long i = ((long long)blockIdx.x * 256 + threadIdx.x) * 4;
    if (i >= N_QKV) return;
    const float* s = (blockIdx.y == 0) ? s0 : (blockIdx.y == 1) ? s1 : s2;
    __nv_bfloat16* h = (blockIdx.y == 0) ? h0 : (blockIdx.y == 1) ? h1 : h2;
    __nv_bfloat16* l = (blockIdx.y == 0) ? l0 : (blockIdx.y == 1) ? l1 : l2;
    split4(s, h, l, i);
}

// 5 weights in one launch (y: 0=Wd big, 1..4=512x512)
__global__ __launch_bounds__(256)
void splitW_kernel(const float* __restrict__ wd, const float* __restrict__ wq,
                   const float* __restrict__ wk, const float* __restrict__ wv,
                   const float* __restrict__ wo,
                   __nv_bfloat16* __restrict__ wdh, __nv_bfloat16* __restrict__ wdl,
                   __nv_bfloat16* __restrict__ wqh, __nv_bfloat16* __restrict__ wql,
                   __nv_bfloat16* __restrict__ wkh, __nv_bfloat16* __restrict__ wkl,
                   __nv_bfloat16* __restrict__ wvh, __nv_bfloat16* __restrict__ wvl,
                   __nv_bfloat16* __restrict__ woh, __nv_bfloat16* __restrict__ wol)
{
    long long i = ((long long)blockIdx.x * 256 + threadIdx.x) * 4;
    const int y = blockIdx.y;
    const long long n = (y == 0) ? (long long)N_WD : (long long)N_W;
    if (i >= n) return;
    const float* s = (y == 0) ? wd : (y == 1) ? wq : (y == 2) ? wk : (y == 3) ? wv : wo;
    __nv_bfloat16* h = (y == 0) ? wdh : (y == 1) ? wqh : (y == 2) ? wkh : (y == 3) ? wvh : woh;
    __nv_bfloat16* l = (y == 0) ? wdl : (y == 1) ? wql : (y == 2) ? wkl : (y == 3) ? wvl : wol;
    split4(s, h, l, i);
}

// ---------------------------------------------------------------------------
// Row softmax over NKEYS, fp32 in -> split bf16 out. One block per row.
// ---------------------------------------------------------------------------
__global__ __launch_bounds__(256)
void softmax_split_kernel(const float* __restrict__ S,
                          __nv_bfloat16* __restrict__ Ph, __nv_bfloat16* __restrict__ Pl)
{
    const float* p = S + (long long)blockIdx.x * NKEYS;
    __nv_bfloat16* ph = Ph + (long long)blockIdx.x * NKEYS;
    __nv_bfloat16* pl = Pl + (long long)blockIdx.x * NKEYS;
    const int tid = threadIdx.x;

    float v[16];
    float m = __int_as_float(0xff800000);
#pragma unroll
    for (int i = 0; i < 16; i++) { v[i] = p[tid + i * 256]; m = fmaxf(m, v[i]); }

    __shared__ float red[256];
    red[tid] = m; __syncthreads();
#pragma unroll
    for (int s = 128; s > 0; s >>= 1) {
        if (tid < s) red[tid] = fmaxf(red[tid], red[tid + s]);
        __syncthreads();
    }
    m = red[0]; __syncthreads();

    float sum = 0.0f;
#pragma unroll
    for (int i = 0; i < 16; i++) { v[i] = __expf(v[i] - m); sum += v[i]; }
    red[tid] = sum; __syncthreads();
#pragma unroll
    for (int s = 128; s > 0; s >>= 1) {
        if (tid < s) red[tid] += red[tid + s];
        __syncthreads();
    }
    const float inv = 1.0f / red[0];
#pragma unroll
    for (int i = 0; i < 16; i++) {
        float pv = v[i] * inv;
        __nv_bfloat16 h = __float2bfloat16_rn(pv);
        ph[tid + i * 256] = h;
        pl[tid + i * 256] = __float2bfloat16_rn(pv - __bfloat162float(h));
    }
}

// ---------------------------------------------------------------------------
// Host dispatch
// ---------------------------------------------------------------------------
#define SMEM_NT (3 * (20480 + 2 * 128 * LDB_NT * 2))
#define SMEM_NN (3 * (20480 + 2 * 32 * LDB_NN * 2))

static void run_gemm3(const __nv_bfloat16* Ah, const __nv_bfloat16* Al,
                      const __nv_bfloat16* Bh, const __nv_bfloat16* Bl,
                      float* Cf, __nv_bfloat16* Ch, __nv_bfloat16* Cl,
                      int M, int N, int K,
                      long long sA, long long sB, long long sC, int batch,
                      bool transB,
                      const float* biasN, const float* biasM, float scale,
                      const int* mask, long long sMask)
{
    dim3 grid(N / 128, M / 128, batch), block(256);
    if (transB)
        gemm3_kernel<true><<<grid, block, SMEM_NT>>>(Ah, Al, Bh, Bl, Cf, Ch, Cl,
            M, N, K, sA, sB, sC, biasN, biasM, scale, mask, sMask);
    else
        gemm3_kernel<false><<<grid, block, SMEM_NN>>>(Ah, Al, Bh, Bl, Cf, Ch, Cl,
            M, N, K, sA, sB, sC, biasN, biasM, scale, mask, sMask);
}

extern "C" void kernel_launch(void* const* d_in, const int* in_sizes, int n_in,
                              void* d_out, int out_size)
{
    (void)in_sizes; (void)n_in; (void)out_size;

    const float* queries = (const float*)d_in[0];
    const float* keys    = (const float*)d_in[1];
    const float* values  = (const float*)d_in[2];
    const int*   mask    = (const int*)d_in[3];
    const float* Wq = (const float*)d_in[4];
    const float* bq = (const float*)d_in[5];
    const float* Wk = (const float*)d_in[6];
    const float* bk = (const float*)d_in[7];
    const float* Wv = (const float*)d_in[8];
    const float* bv = (const float*)d_in[9];
    const float* Wo = (const float*)d_in[10];
    const float* bo = (const float*)d_in[11];
    const float* Wd = (const float*)d_in[12];
    const float* bd = (const float*)d_in[13];
    float* out = (float*)d_out;

    cudaFuncSetAttribute(gemm3_kernel<true>,  cudaFuncAttributeMaxDynamicSharedMemorySize, SMEM_NT);
    cudaFuncSetAttribute(gemm3_kernel<false>, cudaFuncAttributeMaxDynamicSharedMemorySize, SMEM_NN);

    __nv_bfloat16 *qih,*qil,*kih,*kil,*vih,*vil,*wdh,*wdl,*wqh,*wql,*wkh,*wkl,*wvh,*wvl,*woh,*wol;
    __nv_bfloat16 *qdsh,*qdsl,*qh,*ql,*kh,*kl,*vh,*vl,*ph,*pl,*atth,*attl;
    float *sS;
    cudaGetSymbolAddress((void**)&qih, g_qih);   cudaGetSymbolAddress((void**)&qil, g_qil);
    cudaGetSymbolAddress((void**)&kih, g_kih);   cudaGetSymbolAddress((void**)&kil, g_kil);
    cudaGetSymbolAddress((void**)&vih, g_vih);   cudaGetSymbolAddress((void**)&vil, g_vil);
    cudaGetSymbolAddress((void**)&wdh, g_wdh);   cudaGetSymbolAddress((void**)&wdl, g_wdl);
    cudaGetSymbolAddress((void**)&wqh, g_wqh);   cudaGetSymbolAddress((void**)&wql, g_wql);
    cudaGetSymbolAddress((void**)&wkh, g_wkh);   cudaGetSymbolAddress((void**)&wkl, g_wkl);
    cudaGetSymbolAddress((void**)&wvh, g_wvh);   cudaGetSymbolAddress((void**)&wvl, g_wvl);
    cudaGetSymbolAddress((void**)&woh, g_woh);   cudaGetSymbolAddress((void**)&wol, g_wol);
    cudaGetSymbolAddress((void**)&qdsh, g_qdsh); cudaGetSymbolAddress((void**)&qdsl, g_qdsl);
    cudaGetSymbolAddress((void**)&qh, g_qh);     cudaGetSymbolAddress((void**)&ql, g_ql);
    cudaGetSymbolAddress((void**)&kh, g_kh);     cudaGetSymbolAddress((void**)&kl, g_kl);
    cudaGetSymbolAddress((void**)&vh, g_vh);     cudaGetSymbolAddress((void**)&vl, g_vl);
    cudaGetSymbolAddress((void**)&ph, g_ph);     cudaGetSymbolAddress((void**)&pl, g_pl);
    cudaGetSymbolAddress((void**)&atth, g_atth); cudaGetSymbolAddress((void**)&attl, g_attl);
    cudaGetSymbolAddress((void**)&sS, g_s);

    // --- splits: 2 launches total ---
    {
        dim3 g3((N_QKV / 4 + 255) / 256, 3);
        split3_kernel<<<g3, 256>>>(queries, keys, values, qih, qil, kih, kil, vih, vil);
        dim3 gw((N_WD / 4 + 255) / 256, 5);
        splitW_kernel<<<gw, 256>>>(Wd, Wq, Wk, Wv, Wo,
                                   wdh, wdl, wqh, wql, wkh, wkl, wvh, wvl, woh, wol);
    }

    // 1. Downsample (NN): qds[b] = Wd @ queries[b] + bd (row bias)
    run_gemm3(wdh, wdl, qih, qil, nullptr, qdsh, qdsl,
              QAFT, DMODEL, QBEF,
              0, (long long)QBEF * DMODEL, (long long)QAFT * DMODEL, BATCH,
              false, nullptr, bd, 1.0f, nullptr, 0);

    // 2. Q projection (NT): q = qds @ Wq^T + bq
    run_gemm3(qdsh, qdsl, wqh, wql, nullptr, qh, ql,
              BATCH * QAFT, DMODEL, DMODEL, 0, 0, 0, 1,
              true, bq, nullptr, 1.0f, nullptr, 0);

    // 3. K projection
    run_gemm3(kih, kil, wkh, wkl, nullptr, kh, kl,
              BATCH * NKEYS, DMODEL, DMODEL, 0, 0, 0, 1,
              true, bk, nullptr, 1.0f, nullptr, 0);

    // 4. V projection
    run_gemm3(vih, vil, wvh, wvl, nullptr, vh, vl,
              BATCH * NKEYS, DMODEL, DMODEL, 0, 0, 0, 1,
              true, bv, nullptr, 1.0f, nullptr, 0);

    // 5. Scores (NT): s = (q @ k^T)/sqrt(512), masked -> -inf
    run_gemm3(qh, ql, kh, kl, sS, nullptr, nullptr,
              QAFT, NKEYS, DMODEL,
              (long long)QAFT * DMODEL, (long long)NKEYS * DMODEL,
              (long long)QAFT * NKEYS, BATCH,
              true, nullptr, nullptr, 0.044194173824159216f,
              mask, (long long)QAFT * NKEYS);

    // 6. Softmax -> split P
    softmax_split_kernel<<<BATCH * QAFT, 256>>>(sS, ph, pl);

    // 7. PV (NN): att[b] = P[b] @ v[b]
    run_gemm3(ph, pl, vh, vl, nullptr, atth, attl,
              QAFT, DMODEL, NKEYS,
              (long long)QAFT * NKEYS, (long long)NKEYS * DMODEL,
              (long long)QAFT * DMODEL, BATCH,
              false, nullptr, nullptr, 1.0f, nullptr, 0);

    // 8. Output projection (NT) -> fp32 d_out
    run_gemm3(atth, attl, woh, wol, out, nullptr, nullptr,
              BATCH * QAFT, DMODEL, DMODEL, 0, 0, 0, 1,
              true, bo, nullptr, 1.0f, nullptr, 0);
}

// round 9
// speedup vs baseline: 2.3198x; 1.0591x over previous
#include <cuda_runtime.h>
#include <cuda_bf16.h>
#include <cstdint>

// ---------------------------------------------------------------------------
// Problem dims
// ---------------------------------------------------------------------------
#define BATCH  8
#define DMODEL 512
#define QBEF   4096
#define QAFT   1024
#define NKEYS  4096

#define N_QKV  (BATCH * QBEF * DMODEL)
#define N_QDS  (BATCH * QAFT * DMODEL)
#define N_S    (BATCH * QAFT * NKEYS)
#define N_WD   (QAFT * QBEF)
#define N_W    (DMODEL * DMODEL)

__device__ __align__(16) __nv_bfloat16 g_qih[N_QKV], g_qil[N_QKV];
__device__ __align__(16) __nv_bfloat16 g_kih[N_QKV], g_kil[N_QKV];
__device__ __align__(16) __nv_bfloat16 g_vih[N_QKV], g_vil[N_QKV];
__device__ __align__(16) __nv_bfloat16 g_wdh[N_WD],  g_wdl[N_WD];
__device__ __align__(16) __nv_bfloat16 g_wqh[N_W],   g_wql[N_W];
__device__ __align__(16) __nv_bfloat16 g_wkh[N_W],   g_wkl[N_W];
__device__ __align__(16) __nv_bfloat16 g_wvh[N_W],   g_wvl[N_W];
__device__ __align__(16) __nv_bfloat16 g_woh[N_W],   g_wol[N_W];
__device__ __align__(16) __nv_bfloat16 g_qdsh[N_QDS], g_qdsl[N_QDS];
__device__ __align__(16) __nv_bfloat16 g_qh[N_QDS],   g_ql[N_QDS];
__device__ __align__(16) __nv_bfloat16 g_kh[N_QKV],   g_kl[N_QKV];
__device__ __align__(16) __nv_bfloat16 g_vh[N_QKV],   g_vl[N_QKV];
__device__ __align__(16) float         g_s[N_S];
__device__ __align__(16) __nv_bfloat16 g_ph[N_S],     g_pl[N_S];
__device__ __align__(16) __nv_bfloat16 g_atth[N_QDS], g_attl[N_QDS];

// ---------------------------------------------------------------------------
// PTX helpers
// ---------------------------------------------------------------------------
__device__ __forceinline__ void cpasync16(uint32_t dst, const void* src) {
    asm volatile("cp.async.cg.shared.global [%0], [%1], 16;\n" :: "r"(dst), "l"(src));
}
__device__ __forceinline__ void cp_commit() { asm volatile("cp.async.commit_group;\n"); }
__device__ __forceinline__ void cp_wait1()  { asm volatile("cp.async.wait_group 1;\n"); }

__device__ __forceinline__ void ldsm4(uint32_t* r, uint32_t a) {
    asm volatile("ldmatrix.sync.aligned.m8n8.x4.shared.b16 {%0,%1,%2,%3}, [%4];"
        : "=r"(r[0]), "=r"(r[1]), "=r"(r[2]), "=r"(r[3]) : "r"(a));
}
__device__ __forceinline__ void ldsm4t(uint32_t* r, uint32_t a) {
    asm volatile("ldmatrix.sync.aligned.m8n8.x4.trans.shared.b16 {%0,%1,%2,%3}, [%4];"
        : "=r"(r[0]), "=r"(r[1]), "=r"(r[2]), "=r"(r[3]) : "r"(a));
}
__device__ __forceinline__ void mma16816(float* c, const uint32_t* a, const uint32_t* b) {
    asm volatile(
        "mma.sync.aligned.m16n8k16.row.col.f32.bf16.bf16.f32 "
        "{%0,%1,%2,%3}, {%4,%5,%6,%7}, {%8,%9}, {%0,%1,%2,%3};"
        : "+f"(c[0]), "+f"(c[1]), "+f"(c[2]), "+f"(c[3])
        : "r"(a[0]), "r"(a[1]), "r"(a[2]), "r"(a[3]), "r"(b[0]), "r"(b[1]));
}

// ---------------------------------------------------------------------------
// bf16x3 GEMM, tile 128x128, BK=32, 512 threads = 16 warps (4m x 4n),
// warp tile 32x32.  A = Ah+Al [M,K] row-major.  op(B)=B^T if TRANSB
// (B:[N,K]) else B:[K,N].  Output fp32 (Cf) or split bf16 (Ch,Cl).
// ---------------------------------------------------------------------------
#define STAGES 3
#define LDA 40
#define LDB_NT 40
#define LDB_NN 136

template <bool TRANSB>
__global__ __launch_bounds__(512, 1)
void gemm3_kernel(const __nv_bfloat16* __restrict__ Ahg, const __nv_bfloat16* __restrict__ Alg,
                  const __nv_bfloat16* __restrict__ Bhg, const __nv_bfloat16* __restrict__ Blg,
                  float* __restrict__ Cf, __nv_bfloat16* __restrict__ Ch, __nv_bfloat16* __restrict__ Cl,
                  int M, int N, int K,
                  long long sA, long long sB, long long sC,
                  const float* __restrict__ biasN, const float* __restrict__ biasM,
                  float scale, const int* __restrict__ mask, long long sMask)
{
    // Per stage: [Ah 10240][Al 10240][Bh BHALF][Bl BHALF]
    constexpr uint32_t BHALF = TRANSB ? (128u * LDB_NT * 2u) : (32u * LDB_NN * 2u);
    constexpr uint32_t STAGE_BYTES = 20480u + 2u * BHALF;

    extern __shared__ __align__(16) char smem_buf[];
    const int tid  = threadIdx.x;
    const int lane = tid & 31;
    const int warp = tid >> 5;
    const int warpM = warp >> 2;      // 0..3 (32 rows each)
    const int warpN = warp & 3;       // 0..3 (32 cols each)
    const int bz = blockIdx.z;
    const int rowBase = blockIdx.y * 128;
    const int colBase = blockIdx.x * 128;

    const __nv_bfloat16* Ah = Ahg + bz * sA;
    const __nv_bfloat16* Al = Alg + bz * sA;
    const __nv_bfloat16* Bh = Bhg + bz * sB;
    const __nv_bfloat16* Bl = Blg + bz * sB;

    const uint32_t smb = (uint32_t)__cvta_generic_to_shared(smem_buf);

    // Loader: one 16B chunk per thread per operand half (512 chunks each).
    const int aRow = tid >> 2;          // 0..127
    const int aC8  = (tid & 3) * 8;     // 0,8,16,24
    const int bRowNN = tid >> 4;        // 0..31
    const int bC8NN  = (tid & 15) * 8;  // 0..120

    auto load_stage = [&](int kt, int s) {
        const uint32_t base = smb + s * STAGE_BYTES;
        {
            size_t go = (size_t)(rowBase + aRow) * K + kt * 32 + aC8;
            uint32_t d = base + (uint32_t)(aRow * LDA + aC8) * 2;
            cpasync16(d,         Ah + go);
            cpasync16(d + 10240, Al + go);
        }
        if (TRANSB) {
            size_t go = (size_t)(colBase + aRow) * K + kt * 32 + aC8;
            uint32_t d = base + 20480 + (uint32_t)(aRow * LDB_NT + aC8) * 2;
            cpasync16(d,         Bh + go);
            cpasync16(d + BHALF, Bl + go);
        } else {
            size_t go = (size_t)(kt * 32 + bRowNN) * N + colBase + bC8NN;
            uint32_t d = base + 20480 + (uint32_t)(bRowNN * LDB_NN + bC8NN) * 2;
            cpasync16(d,         Bh + go);
            cpasync16(d + BHALF, Bl + go);
        }
    };

    // ldmatrix per-thread address components
    const int a_row = warpM * 32 + (lane & 15);
    const int a_col = ((lane >> 4) << 3);
    const uint32_t a_off = (uint32_t)(a_row * LDA + a_col) * 2;

    uint32_t b_off;
    if (TRANSB) {
        int b_n = warpN * 32 + (lane & 7) + ((lane >> 4) << 3);
        int b_k = ((lane >> 3) & 1) * 8;
        b_off = (uint32_t)(b_n * LDB_NT + b_k) * 2;
    } else {
        int b_k = lane & 15;
        int b_n = warpN * 32 + ((lane >> 4) << 3);
        b_off = (uint32_t)(b_k * LDB_NN + b_n) * 2;
    }

    float acc[2][4][4];
#pragma unroll
    for (int mt = 0; mt < 2; mt++)
#pragma unroll
        for (int nt = 0; nt < 4; nt++)
#pragma unroll
            for (int i = 0; i < 4; i++) acc[mt][nt][i] = 0.0f;

    const int nkt = K / 32;

    load_stage(0, 0); cp_commit();
    load_stage(1, 1); cp_commit();

    for (int kt = 0; kt < nkt; kt++) {
        cp_wait1();
        __syncthreads();

        int ls = kt + STAGES - 1;
        if (ls < nkt) load_stage(ls, ls % STAGES);
        cp_commit();

        const uint32_t sb = smb + (kt % STAGES) * STAGE_BYTES;
#pragma unroll
        for (int kk = 0; kk < 2; kk++) {
            uint32_t ah[2][4], al[2][4], bh[2][4], bl[2][4];
#pragma unroll
            for (int mt = 0; mt < 2; mt++) {
                uint32_t ao = sb + a_off + (uint32_t)(mt * 16 * LDA + kk * 16) * 2;
                ldsm4(ah[mt], ao);
                ldsm4(al[mt], ao + 10240);
            }
#pragma unroll
            for (int g4 = 0; g4 < 2; g4++) {
                if (TRANSB) {
                    uint32_t bo = sb + 20480 + b_off + (uint32_t)(g4 * 16 * LDB_NT + kk * 16) * 2;
                    ldsm4(bh[g4], bo);
                    ldsm4(bl[g4], bo + BHALF);
                } else {
                    uint32_t bo = sb + 20480 + b_off + (uint32_t)(kk * 16 * LDB_NN + g4 * 16) * 2;
                    ldsm4t(bh[g4], bo);
                    ldsm4t(bl[g4], bo + BHALF);
                }
            }
            // Term-major ordering: 8 independent accumulators between reuses.
#pragma unroll
            for (int mt = 0; mt < 2; mt++)
#pragma unroll
                for (int nt = 0; nt < 4; nt++) {
                    const int g4 = nt >> 1, hf = (nt & 1) * 2;
                    uint32_t bH[2] = { bh[g4][hf], bh[g4][hf + 1] };
                    mma16816(acc[mt][nt], ah[mt], bH);
                }
#pragma unroll
            for (int mt = 0; mt < 2; mt++)
#pragma unroll
                for (int nt = 0; nt < 4; nt++) {
                    const int g4 = nt >> 1, hf = (nt & 1) * 2;
                    uint32_t bL[2] = { bl[g4][hf], bl[g4][hf + 1] };
                    mma16816(acc[mt][nt], ah[mt], bL);
                }
#pragma unroll
            for (int mt = 0; mt < 2; mt++)
#pragma unroll
                for (int nt = 0; nt < 4; nt++) {
                    const int g4 = nt >> 1, hf = (nt & 1) * 2;
                    uint32_t bH[2] = { bh[g4][hf], bh[g4][hf + 1] };
                    mma16816(acc[mt][nt], al[mt], bH);
                }
        }
        __syncthreads();
    }

    // Epilogue
    const int g = lane >> 2, t = lane & 3;
    float* CfB = Cf ? (Cf + bz * sC) : nullptr;
    __nv_bfloat16* ChB = Ch ? (Ch + bz * sC) : nullptr;
    __nv_bfloat16* ClB = Cl ? (Cl + bz * sC) : nullptr;
    const int* maskB = mask ? (mask + bz * sMask) : nullptr;

#pragma unroll
    for (int mt = 0; mt < 2; mt++) {
#pragma unroll
        for (int nt = 0; nt < 4; nt++) {
            const int r0 = rowBase + warpM * 32 + mt * 16 + g;
            const int r1 = r0 + 8;
            const int cc = colBase + warpN * 32 + nt * 8 + 2 * t;
            float v00 = acc[mt][nt][0] * scale;
            float v01 = acc[mt][nt][1] * scale;
            float v10 = acc[mt][nt][2] * scale;
            float v11 = acc[mt][nt][3] * scale;
            if (biasM) {
                float b0 = biasM[r0], b1 = biasM[r1];
                v00 += b0; v01 += b0; v10 += b1; v11 += b1;
            }
            if (biasN) {
                float b0 = biasN[cc], b1 = biasN[cc + 1];
                v00 += b0; v01 += b1; v10 += b0; v11 += b1;
            }
            if (maskB) {
                const float NINF = __int_as_float(0xff800000);
                if (maskB[(long long)r0 * N + cc])     v00 = NINF;
                if (maskB[(long long)r0 * N + cc + 1]) v01 = NINF;
                if (maskB[(long long)r1 * N + cc])     v10 = NINF;
                if (maskB[(long long)r1 * N + cc + 1]) v11 = NINF;
            }
            if (CfB) {
                *(float2*)(CfB + (long long)r0 * N + cc) = make_float2(v00, v01);
                *(float2*)(CfB + (long long)r1 * N + cc) = make_float2(v10, v11);
            } else {
                __nv_bfloat16 h00 = __float2bfloat16_rn(v00);
                __nv_bfloat16 h01 = __float2bfloat16_rn(v01);
                __nv_bfloat16 h10 = __float2bfloat16_rn(v10);
                __nv_bfloat16 h11 = __float2bfloat16_rn(v11);
                __nv_bfloat162 H0; H0.x = h00; H0.y = h01;
                __nv_bfloat162 H1; H1.x = h10; H1.y = h11;
                __nv_bfloat162 L0, L1;
                L0.x = __float2bfloat16_rn(v00 - __bfloat162float(h00));
                L0.y = __float2bfloat16_rn(v01 - __bfloat162float(h01));
                L1.x = __float2bfloat16_rn(v10 - __bfloat162float(h10));
                L1.y = __float2bfloat16_rn(v11 - __bfloat162float(h11));
                *(__nv_bfloat162*)(ChB + (long long)r0 * N + cc) = H0;
                *(__nv_bfloat162*)(ChB + (long long)r1 * N + cc) = H1;
                *(__nv_bfloat162*)(ClB + (long long)r0 * N + cc) = L0;
                *(__nv_bfloat162*)(ClB + (long long)r1 * N + cc) = L1;
            }
        }
    }
}

// ---------------------------------------------------------------------------
// Fused splits: fp32 -> bf16 hi/lo
// ---------------------------------------------------------------------------
__device__ __forceinline__ void split4(const float* src, __nv_bfloat16* h,
                                       __nv_bfloat16* l, long long i)
{
    float4 v = *(const float4*)(src + i);
    __nv_bfloat16 h0 = __float2bfloat16_rn(v.x);
    __nv_bfloat16 h1 = __float2bfloat16_rn(v.y);
    __nv_bfloat16 h2 = __float2bfloat16_rn(v.z);
    __nv_bfloat16 h3 = __float2bfloat16_rn(v.w);
    __nv_bfloat162 H0; H0.x = h0; H0.y = h1;
    __nv_bfloat162 H1; H1.x = h2; H1.y = h3;
    __nv_bfloat162 L0, L1;
    L0.x = __float2bfloat16_rn(v.x - __bfloat162float(h0));
    L0.y = __float2bfloat16_rn(v.y - __bfloat162float(h1));
    L1.x = __float2bfloat16_rn(v.z - __bfloat162float(h2));
    L1.y = __float2bfloat16_rn(v.w - __bfloat162float(h3));
    *(__nv_bfloat162*)(h + i)     = H0;
    *(__nv_bfloat162*)(h + i + 2) = H1;
    *(__nv_bfloat162*)(l + i)     = L0;
    *(__nv_bfloat162*)(l + i + 2) = L1;
}

__global__ __launch_bounds__(256)
void split3_kernel(const float* __restrict__ s0, const float* __restrict__ s1,
                   const float* __restrict__ s2,
                   __nv_bfloat16* __restrict__ h0, __nv_bfloat16* __restrict__ l0,
                   __nv_bfloat16* __restrict__ h1, __nv_bfloat16* __restrict__ l1,
                   __nv_bfloat16* __restrict__ h2, __nv_bfloat16* __restrict__ l2)
{
    long long i = ((long long)blockIdx.x * 256 + threadIdx.x) * 4;
    if (i >= N_QKV) return;
    const float* s = (blockIdx.y == 0) ? s0 : (blockIdx.y == 1) ? s1 : s2;
    __nv_bfloat16* h = (blockIdx.y == 0) ? h0 : (blockIdx.y == 1) ? h1 : h2;
    __nv_bfloat16* l = (blockIdx.y == 0) ? l0 : (blockIdx.y == 1) ? l1 : l2;
    split4(s, h, l, i);
}

__global__ __launch_bounds__(256)
void splitW_kernel(const float* __restrict__ wd, const float* __restrict__ wq,
                   const float* __restrict__ wk, const float* __restrict__ wv,
                   const float* __restrict__ wo,
                   __nv_bfloat16* __restrict__ wdh, __nv_bfloat16* __restrict__ wdl,
                   __nv_bfloat16* __restrict__ wqh, __nv_bfloat16* __restrict__ wql,
                   __nv_bfloat16* __restrict__ wkh, __nv_bfloat16* __restrict__ wkl,
                   __nv_bfloat16* __restrict__ wvh, __nv_bfloat16* __restrict__ wvl,
                   __nv_bfloat16* __restrict__ woh, __nv_bfloat16* __restrict__ wol)
{
    long long i = ((long long)blockIdx.x * 256 + threadIdx.x) * 4;
    const int y = blockIdx.y;
    const long long n = (y == 0) ? (long long)N_WD : (long long)N_W;
    if (i >= n) return;
    const float* s = (y == 0) ? wd : (y == 1) ? wq : (y == 2) ? wk : (y == 3) ? wv : wo;
    __nv_bfloat16* h = (y == 0) ? wdh : (y == 1) ? wqh : (y == 2) ? wkh : (y == 3) ? wvh : woh;
    __nv_bfloat16* l = (y == 0) ? wdl : (y == 1) ? wql : (y == 2) ? wkl : (y == 3) ? wvl : wol;
    split4(s, h, l, i);
}

// ---------------------------------------------------------------------------
// Row softmax over NKEYS, fp32 in -> split bf16 out. One block per row.
// ---------------------------------------------------------------------------
__global__ __launch_bounds__(256)
void softmax_split_kernel(const float* __restrict__ S,
                          __nv_bfloat16* __restrict__ Ph, __nv_bfloat16* __restrict__ Pl)
{
    const float* p = S + (long long)blockIdx.x * NKEYS;
    __nv_bfloat16* ph = Ph + (long long)blockIdx.x * NKEYS;
    __nv_bfloat16* pl = Pl + (long long)blockIdx.x * NKEYS;
    const int tid = threadIdx.x;

    float v[16];
    float m = __int_as_float(0xff800000);
#pragma unroll
    for (int i = 0; i < 16; i++) { v[i] = p[tid + i * 256]; m = fmaxf(m, v[i]); }

    __shared__ float red[256];
    red[tid] = m; __syncthreads();
#pragma unroll
    for (int s = 128; s > 0; s >>= 1) {
        if (tid < s) red[tid] = fmaxf(red[tid], red[tid + s]);
        __syncthreads();
    }
    m = red[0]; __syncthreads();

    float sum = 0.0f;
#pragma unroll
    for (int i = 0; i < 16; i++) { v[i] = __expf(v[i] - m); sum += v[i]; }
    red[tid] = sum; __syncthreads();
#pragma unroll
    for (int s = 128; s > 0; s >>= 1) {
        if (tid < s) red[tid] += red[tid + s];
        __syncthreads();
    }
    const float inv = 1.0f / red[0];
#pragma unroll
    for (int i = 0; i < 16; i++) {
        float pv = v[i] * inv;
        __nv_bfloat16 h = __float2bfloat16_rn(pv);
        ph[tid + i * 256] = h;
        pl[tid + i * 256] = __float2bfloat16_rn(pv - __bfloat162float(h));
    }
}

// ---------------------------------------------------------------------------
// Host dispatch
// ---------------------------------------------------------------------------
#define SMEM_NT (3 * (20480 + 2 * 128 * LDB_NT * 2))
#define SMEM_NN (3 * (20480 + 2 * 32 * LDB_NN * 2))

static void run_gemm3(const __nv_bfloat16* Ah, const __nv_bfloat16* Al,
                      const __nv_bfloat16* Bh, const __nv_bfloat16* Bl,
                      float* Cf, __nv_bfloat16* Ch, __nv_bfloat16* Cl,
                      int M, int N, int K,
                      long long sA, long long sB, long long sC, int batch,
                      bool transB,
                      const float* biasN, const float* biasM, float scale,
                      const int* mask, long long sMask)
{
    dim3 grid(N / 128, M / 128, batch), block(512);
    if (transB)
        gemm3_kernel<true><<<grid, block, SMEM_NT>>>(Ah, Al, Bh, Bl, Cf, Ch, Cl,
            M, N, K, sA, sB, sC, biasN, biasM, scale, mask, sMask);
    else
        gemm3_kernel<false><<<grid, block, SMEM_NN>>>(Ah, Al, Bh, Bl, Cf, Ch, Cl,
            M, N, K, sA, sB, sC, biasN, biasM, scale, mask, sMask);
}

extern "C" void kernel_launch(void* const* d_in, const int* in_sizes, int n_in,
                              void* d_out, int out_size)
{
    (void)in_sizes; (void)n_in; (void)out_size;

    const float* queries = (const float*)d_in[0];
    const float* keys    = (const float*)d_in[1];
    const float* values  = (const float*)d_in[2];
    const int*   mask    = (const int*)d_in[3];
    const float* Wq = (const float*)d_in[4];
    const float* bq = (const float*)d_in[5];
    const float* Wk = (const float*)d_in[6];
    const float* bk = (const float*)d_in[7];
    const float* Wv = (const float*)d_in[8];
    const float* bv = (const float*)d_in[9];
    const float* Wo = (const float*)d_in[10];
    const float* bo = (const float*)d_in[11];
    const float* Wd = (const float*)d_in[12];
    const float* bd = (const float*)d_in[13];
    float* out = (float*)d_out;

    cudaFuncSetAttribute(gemm3_kernel<true>,  cudaFuncAttributeMaxDynamicSharedMemorySize, SMEM_NT);
    cudaFuncSetAttribute(gemm3_kernel<false>, cudaFuncAttributeMaxDynamicSharedMemorySize, SMEM_NN);

    __nv_bfloat16 *qih,*qil,*kih,*kil,*vih,*vil,*wdh,*wdl,*wqh,*wql,*wkh,*wkl,*wvh,*wvl,*woh,*wol;
    __nv_bfloat16 *qdsh,*qdsl,*qh,*ql,*kh,*kl,*vh,*vl,*ph,*pl,*atth,*attl;
    float *sS;
    cudaGetSymbolAddress((void**)&qih, g_qih);   cudaGetSymbolAddress((void**)&qil, g_qil);
    cudaGetSymbolAddress((void**)&kih, g_kih);   cudaGetSymbolAddress((void**)&kil, g_kil);
    cudaGetSymbolAddress((void**)&vih, g_vih);   cudaGetSymbolAddress((void**)&vil, g_vil);
    cudaGetSymbolAddress((void**)&wdh, g_wdh);   cudaGetSymbolAddress((void**)&wdl, g_wdl);
    cudaGetSymbolAddress((void**)&wqh, g_wqh);   cudaGetSymbolAddress((void**)&wql, g_wql);
    cudaGetSymbolAddress((void**)&wkh, g_wkh);   cudaGetSymbolAddress((void**)&wkl, g_wkl);
    cudaGetSymbolAddress((void**)&wvh, g_wvh);   cudaGetSymbolAddress((void**)&wvl, g_wvl);
    cudaGetSymbolAddress((void**)&woh, g_woh);   cudaGetSymbolAddress((void**)&wol, g_wol);
    cudaGetSymbolAddress((void**)&qdsh, g_qdsh); cudaGetSymbolAddress((void**)&qdsl, g_qdsl);
    cudaGetSymbolAddress((void**)&qh, g_qh);     cudaGetSymbolAddress((void**)&ql, g_ql);
    cudaGetSymbolAddress((void**)&kh, g_kh);     cudaGetSymbolAddress((void**)&kl, g_kl);
    cudaGetSymbolAddress((void**)&vh, g_vh);     cudaGetSymbolAddress((void**)&vl, g_vl);
    cudaGetSymbolAddress((void**)&ph, g_ph);     cudaGetSymbolAddress((void**)&pl, g_pl);
    cudaGetSymbolAddress((void**)&atth, g_atth); cudaGetSymbolAddress((void**)&attl, g_attl);
    cudaGetSymbolAddress((void**)&sS, g_s);

    // splits: 2 launches
    {
        dim3 g3((N_QKV / 4 + 255) / 256, 3);
        split3_kernel<<<g3, 256>>>(queries, keys, values, qih, qil, kih, kil, vih, vil);
        dim3 gw((N_WD / 4 + 255) / 256, 5);
        splitW_kernel<<<gw, 256>>>(Wd, Wq, Wk, Wv, Wo,
                                   wdh, wdl, wqh, wql, wkh, wkl, wvh, wvl, woh, wol);
    }

    // 1. Downsample (NN): qds[b] = Wd @ queries[b] + bd (row bias)
    run_gemm3(wdh, wdl, qih, qil, nullptr, qdsh, qdsl,
              QAFT, DMODEL, QBEF,
              0, (long long)QBEF * DMODEL, (long long)QAFT * DMODEL, BATCH,
              false, nullptr, bd, 1.0f, nullptr, 0);

    // 2. Q projection (NT): q = qds @ Wq^T + bq
    run_gemm3(qdsh, qdsl, wqh, wql, nullptr, qh, ql,
              BATCH * QAFT, DMODEL, DMODEL, 0, 0, 0, 1,
              true, bq, nullptr, 1.0f, nullptr, 0);

    // 3. K projection
    run_gemm3(kih, kil, wkh, wkl, nullptr, kh, kl,
              BATCH * NKEYS, DMODEL, DMODEL, 0, 0, 0, 1,
              true, bk, nullptr, 1.0f, nullptr, 0);

    // 4. V projection
    run_gemm3(vih, vil, wvh, wvl, nullptr, vh, vl,
              BATCH * NKEYS, DMODEL, DMODEL, 0, 0, 0, 1,
              true, bv, nullptr, 1.0f, nullptr, 0);

    // 5. Scores (NT): s = (q @ k^T)/sqrt(512), masked -> -inf
    run_gemm3(qh, ql, kh, kl, sS, nullptr, nullptr,
              QAFT, NKEYS, DMODEL,
              (long long)QAFT * DMODEL, (long long)NKEYS * DMODEL,
              (long long)QAFT * NKEYS, BATCH,
              true, nullptr, nullptr, 0.044194173824159216f,
              mask, (long long)QAFT * NKEYS);

    // 6. Softmax -> split P
    softmax_split_kernel<<<BATCH * QAFT, 256>>>(sS, ph, pl);

    // 7. PV (NN): att[b] = P[b] @ v[b]
    run_gemm3(ph, pl, vh, vl, nullptr, atth, attl,
              QAFT, DMODEL, NKEYS,
              (long long)QAFT * NKEYS, (long long)NKEYS * DMODEL,
              (long long)QAFT * DMODEL, BATCH,
              false, nullptr, nullptr, 1.0f, nullptr, 0);

    // 8. Output projection (NT) -> fp32 d_out
    run_gemm3(atth, attl, woh, wol, out, nullptr, nullptr,
              BATCH * QAFT, DMODEL, DMODEL, 0, 0, 0, 1,
              true, bo, nullptr, 1.0f, nullptr, 0);
}

// round 11
// speedup vs baseline: 2.4151x; 1.0411x over previous
#include <cuda_runtime.h>
#include <cuda_bf16.h>
#include <cstdint>

// ---------------------------------------------------------------------------
// Problem dims
// ---------------------------------------------------------------------------
#define BATCH  8
#define DMODEL 512
#define QBEF   4096
#define QAFT   1024
#define NKEYS  4096

#define N_QKV  (BATCH * QBEF * DMODEL)
#define N_QDS  (BATCH * QAFT * DMODEL)
#define N_S    (BATCH * QAFT * NKEYS)
#define N_WD   (QAFT * QBEF)
#define N_W    (DMODEL * DMODEL)

__device__ __align__(16) __nv_bfloat16 g_qih[N_QKV], g_qil[N_QKV];
__device__ __align__(16) __nv_bfloat16 g_kih[N_QKV], g_kil[N_QKV];
__device__ __align__(16) __nv_bfloat16 g_vih[N_QKV], g_vil[N_QKV];
__device__ __align__(16) __nv_bfloat16 g_wdh[N_WD],  g_wdl[N_WD];
__device__ __align__(16) __nv_bfloat16 g_wqh[N_W],   g_wql[N_W];
__device__ __align__(16) __nv_bfloat16 g_wkh[N_W],   g_wkl[N_W];
__device__ __align__(16) __nv_bfloat16 g_wvh[N_W],   g_wvl[N_W];
__device__ __align__(16) __nv_bfloat16 g_woh[N_W],   g_wol[N_W];
__device__ __align__(16) __nv_bfloat16 g_qdsh[N_QDS], g_qdsl[N_QDS];
__device__ __align__(16) __nv_bfloat16 g_qh[N_QDS],   g_ql[N_QDS];
__device__ __align__(16) __nv_bfloat16 g_kh[N_QKV],   g_kl[N_QKV];
__device__ __align__(16) __nv_bfloat16 g_vh[N_QKV],   g_vl[N_QKV];
__device__ __align__(16) float         g_s[N_S];
__device__ __align__(16) __nv_bfloat16 g_ph[N_S],     g_pl[N_S];
__device__ __align__(16) __nv_bfloat16 g_atth[N_QDS], g_attl[N_QDS];

// ---------------------------------------------------------------------------
// PTX helpers
// ---------------------------------------------------------------------------
__device__ __forceinline__ void cpasync16(uint32_t dst, const void* src) {
    asm volatile("cp.async.cg.shared.global [%0], [%1], 16;\n" :: "r"(dst), "l"(src));
}
__device__ __forceinline__ void cp_commit() { asm volatile("cp.async.commit_group;\n"); }
__device__ __forceinline__ void cp_wait1()  { asm volatile("cp.async.wait_group 1;\n" ::: "memory"); }
__device__ __forceinline__ void cp_wait0()  { asm volatile("cp.async.wait_group 0;\n" ::: "memory"); }

__device__ __forceinline__ void ldsm4(uint32_t* r, uint32_t a) {
    asm volatile("ldmatrix.sync.aligned.m8n8.x4.shared.b16 {%0,%1,%2,%3}, [%4];"
        : "=r"(r[0]), "=r"(r[1]), "=r"(r[2]), "=r"(r[3]) : "r"(a));
}
__device__ __forceinline__ void ldsm4t(uint32_t* r, uint32_t a) {
    asm volatile("ldmatrix.sync.aligned.m8n8.x4.trans.shared.b16 {%0,%1,%2,%3}, [%4];"
        : "=r"(r[0]), "=r"(r[1]), "=r"(r[2]), "=r"(r[3]) : "r"(a));
}
__device__ __forceinline__ void mma16816(float* c, const uint32_t* a, const uint32_t* b) {
    asm volatile(
        "mma.sync.aligned.m16n8k16.row.col.f32.bf16.bf16.f32 "
        "{%0,%1,%2,%3}, {%4,%5,%6,%7}, {%8,%9}, {%0,%1,%2,%3};"
        : "+f"(c[0]), "+f"(c[1]), "+f"(c[2]), "+f"(c[3])
        : "r"(a[0]), "r"(a[1]), "r"(a[2]), "r"(a[3]), "r"(b[0]), "r"(b[1]));
}

// ---------------------------------------------------------------------------
// bf16x3 GEMM, tile 128x64, BK=32, 256 threads = 8 warps (4m x 2n),
// warp tile 32x32.  2-stage cp.async pipeline; target 3 CTAs/SM.
// A = Ah+Al [M,K] row-major.  op(B)=B^T if TRANSB (B:[N,K]) else B:[K,N].
// Output fp32 (Cf) or split bf16 (Ch,Cl).
// ---------------------------------------------------------------------------
#define LDA 40
#define LDB_NT 40
#define LDB_NN 72
#define AB_OFF 20480u

template <bool TRANSB>
__global__ __launch_bounds__(256, 3)
void gemm3_kernel(const __nv_bfloat16* __restrict__ Ahg, const __nv_bfloat16* __restrict__ Alg,
                  const __nv_bfloat16* __restrict__ Bhg, const __nv_bfloat16* __restrict__ Blg,
                  float* __restrict__ Cf, __nv_bfloat16* __restrict__ Ch, __nv_bfloat16* __restrict__ Cl,
                  int M, int N, int K,
                  long long sA, long long sB, long long sC,
                  const float* __restrict__ biasN, const float* __restrict__ biasM,
                  float scale, const int* __restrict__ mask, long long sMask)
{
    // Per stage: [Ah 10240][Al 10240][Bh BHALF][Bl BHALF]
    constexpr uint32_t BHALF = TRANSB ? (64u * LDB_NT * 2u) : (32u * LDB_NN * 2u);
    constexpr uint32_t STAGE_BYTES = AB_OFF + 2u * BHALF;

    extern __shared__ __align__(16) char smem_buf[];
    const int tid  = threadIdx.x;
    const int lane = tid & 31;
    const int warp = tid >> 5;
    const int warpM = warp >> 1;      // 0..3 (32 rows)
    const int warpN = warp & 1;       // 0..1 (32 cols)
    const int bz = blockIdx.z;
    const int rowBase = blockIdx.y * 128;
    const int colBase = blockIdx.x * 64;

    const __nv_bfloat16* Ah = Ahg + bz * sA;
    const __nv_bfloat16* Al = Alg + bz * sA;
    const __nv_bfloat16* Bh = Bhg + bz * sB;
    const __nv_bfloat16* Bl = Blg + bz * sB;

    const uint32_t smb = (uint32_t)__cvta_generic_to_shared(smem_buf);

    auto load_stage = [&](int kt, int s) {
        const uint32_t base = smb + s * STAGE_BYTES;
#pragma unroll
        for (int i = 0; i < 2; i++) {          // A: 512 chunks of 16B
            int idx = tid + i * 256;
            int row = idx >> 2, c8 = (idx & 3) * 8;
            size_t go = (size_t)(rowBase + row) * K + kt * 32 + c8;
            uint32_t d = base + (uint32_t)(row * LDA + c8) * 2;
            cpasync16(d,         Ah + go);
            cpasync16(d + 10240, Al + go);
        }
        if (TRANSB) {                          // B: 256 chunks
            int n = tid >> 2, c8 = (tid & 3) * 8;
            size_t go = (size_t)(colBase + n) * K + kt * 32 + c8;
            uint32_t d = base + AB_OFF + (uint32_t)(n * LDB_NT + c8) * 2;
            cpasync16(d,         Bh + go);
            cpasync16(d + BHALF, Bl + go);
        } else {
            int k = tid >> 3, c8 = (tid & 7) * 8;
            size_t go = (size_t)(kt * 32 + k) * N + colBase + c8;
            uint32_t d = base + AB_OFF + (uint32_t)(k * LDB_NN + c8) * 2;
            cpasync16(d,         Bh + go);
            cpasync16(d + BHALF, Bl + go);
        }
    };

    // ldmatrix per-thread address components
    const int a_row = warpM * 32 + (lane & 15);
    const int a_col = ((lane >> 4) << 3);
    const uint32_t a_off = (uint32_t)(a_row * LDA + a_col) * 2;

    uint32_t b_off;
    if (TRANSB) {
        int b_n = warpN * 32 + (lane & 7) + ((lane >> 4) << 3);
        int b_k = ((lane >> 3) & 1) * 8;
        b_off = (uint32_t)(b_n * LDB_NT + b_k) * 2;
    } else {
        int b_k = lane & 15;
        int b_n = warpN * 32 + ((lane >> 4) << 3);
        b_off = (uint32_t)(b_k * LDB_NN + b_n) * 2;
    }

    float acc[2][4][4];
#pragma unroll
    for (int mt = 0; mt < 2; mt++)
#pragma unroll
        for (int nt = 0; nt < 4; nt++)
#pragma unroll
            for (int i = 0; i < 4; i++) acc[mt][nt][i] = 0.0f;

    const int nkt = K / 32;

    load_stage(0, 0); cp_commit();

    for (int kt = 0; kt < nkt; kt++) {
        const bool more = (kt + 1 < nkt);
        if (more) { load_stage(kt + 1, (kt + 1) & 1); cp_commit(); cp_wait1(); }
        else      { cp_wait0(); }
        __syncthreads();

        const uint32_t sb = smb + (kt & 1) * STAGE_BYTES;
#pragma unroll
        for (int kk = 0; kk < 2; kk++) {
            uint32_t ah[2][4], al[2][4], bh[2][4], bl[2][4];
#pragma unroll
            for (int mt = 0; mt < 2; mt++) {
                uint32_t ao = sb + a_off + (uint32_t)(mt * 16 * LDA + kk * 16) * 2;
                ldsm4(ah[mt], ao);
                ldsm4(al[mt], ao + 10240);
            }
#pragma unroll
            for (int g4 = 0; g4 < 2; g4++) {
                if (TRANSB) {
                    uint32_t bo = sb + AB_OFF + b_off + (uint32_t)(g4 * 16 * LDB_NT + kk * 16) * 2;
                    ldsm4(bh[g4], bo);
                } else {
                    uint32_t bo = sb + AB_OFF + b_off + (uint32_t)(kk * 16 * LDB_NN + g4 * 16) * 2;
                    ldsm4t(bh[g4], bo);
                }
            }
            // term 1: Ah*Bh
#pragma unroll
            for (int mt = 0; mt < 2; mt++)
#pragma unroll
                for (int nt = 0; nt < 4; nt++) {
                    const int g4 = nt >> 1, hf = (nt & 1) * 2;
                    uint32_t bH[2] = { bh[g4][hf], bh[g4][hf + 1] };
                    mma16816(acc[mt][nt], ah[mt], bH);
                }
            // term 2: Al*Bh  (Al dead after this)
#pragma unroll
            for (int mt = 0; mt < 2; mt++)
#pragma unroll
                for (int nt = 0; nt < 4; nt++) {
                    const int g4 = nt >> 1, hf = (nt & 1) * 2;
                    uint32_t bH[2] = { bh[g4][hf], bh[g4][hf + 1] };
                    mma16816(acc[mt][nt], al[mt], bH);
                }
            // load Bl late (keeps peak live frags low), term 3: Ah*Bl
#pragma unroll
            for (int g4 = 0; g4 < 2; g4++) {
                if (TRANSB) {
                    uint32_t bo = sb + AB_OFF + b_off + (uint32_t)(g4 * 16 * LDB_NT + kk * 16) * 2;
                    ldsm4(bl[g4], bo + BHALF);
                } else {
                    uint32_t bo = sb + AB_OFF + b_off + (uint32_t)(kk * 16 * LDB_NN + g4 * 16) * 2;
                    ldsm4t(bl[g4], bo + BHALF);
                }
            }
#pragma unroll
            for (int mt = 0; mt < 2; mt++)
#pragma unroll
                for (int nt = 0; nt < 4; nt++) {
                    const int g4 = nt >> 1, hf = (nt & 1) * 2;
                    uint32_t bL[2] = { bl[g4][hf], bl[g4][hf + 1] };
                    mma16816(acc[mt][nt], ah[mt], bL);
                }
        }
        __syncthreads();
    }

    // Epilogue
    const int g = lane >> 2, t = lane & 3;
    float* CfB = Cf ? (Cf + bz * sC) : nullptr;
    __nv_bfloat16* ChB = Ch ? (Ch + bz * sC) : nullptr;
    __nv_bfloat16* ClB = Cl ? (Cl + bz * sC) : nullptr;
    const int* maskB = mask ? (mask + bz * sMask) : nullptr;

#pragma unroll
    for (int mt = 0; mt < 2; mt++) {
#pragma unroll
        for (int nt = 0; nt < 4; nt++) {
            const int r0 = rowBase + warpM * 32 + mt * 16 + g;
            const int r1 = r0 + 8;
            const int cc = colBase + warpN * 32 + nt * 8 + 2 * t;
            float v00 = acc[mt][nt][0] * scale;
            float v01 = acc[mt][nt][1] * scale;
            float v10 = acc[mt][nt][2] * scale;
            float v11 = acc[mt][nt][3] * scale;
            if (biasM) {
                float b0 = biasM[r0], b1 = biasM[r1];
                v00 += b0; v01 += b0; v10 += b1; v11 += b1;
            }
            if (biasN) {
                float b0 = biasN[cc], b1 = biasN[cc + 1];
                v00 += b0; v01 += b1; v10 += b0; v11 += b1;
            }
            if (maskB) {
                const float NINF = __int_as_float(0xff800000);
                if (maskB[(long long)r0 * N + cc])     v00 = NINF;
                if (maskB[(long long)r0 * N + cc + 1]) v01 = NINF;
                if (maskB[(long long)r1 * N + cc])     v10 = NINF;
                if (maskB[(long long)r1 * N + cc + 1]) v11 = NINF;
            }
            if (CfB) {
                *(float2*)(CfB + (long long)r0 * N + cc) = make_float2(v00, v01);
                *(float2*)(CfB + (long long)r1 * N + cc) = make_float2(v10, v11);
            } else {
                __nv_bfloat16 h00 = __float2bfloat16_rn(v00);
                __nv_bfloat16 h01 = __float2bfloat16_rn(v01);
                __nv_bfloat16 h10 = __float2bfloat16_rn(v10);
                __nv_bfloat16 h11 = __float2bfloat16_rn(v11);
                __nv_bfloat162 H0; H0.x = h00; H0.y = h01;
                __nv_bfloat162 H1; H1.x = h10; H1.y = h11;
                __nv_bfloat162 L0, L1;
                L0.x = __float2bfloat16_rn(v00 - __bfloat162float(h00));
                L0.y = __float2bfloat16_rn(v01 - __bfloat162float(h01));
                L1.x = __float2bfloat16_rn(v10 - __bfloat162float(h10));
                L1.y = __float2bfloat16_rn(v11 - __bfloat162float(h11));
                *(__nv_bfloat162*)(ChB + (long long)r0 * N + cc) = H0;
                *(__nv_bfloat162*)(ChB + (long long)r1 * N + cc) = H1;
                *(__nv_bfloat162*)(ClB + (long long)r0 * N + cc) = L0;
                *(__nv_bfloat162*)(ClB + (long long)r1 * N + cc) = L1;
            }
        }
    }
}

// ---------------------------------------------------------------------------
// Fused splits: fp32 -> bf16 hi/lo
// ---------------------------------------------------------------------------
__device__ __forceinline__ void split4(const float* src, __nv_bfloat16* h,
                                       __nv_bfloat16* l, long long i)
{
    float4 v = *(const float4*)(src + i);
    __nv_bfloat16 h0 = __float2bfloat16_rn(v.x);
    __nv_bfloat16 h1 = __float2bfloat16_rn(v.y);
    __nv_bfloat16 h2 = __float2bfloat16_rn(v.z);
    __nv_bfloat16 h3 = __float2bfloat16_rn(v.w);
    __nv_bfloat162 H0; H0.x = h0; H0.y = h1;
    __nv_bfloat162 H1; H1.x = h2; H1.y = h3;
    __nv_bfloat162 L0, L1;
    L0.x = __float2bfloat16_rn(v.x - __bfloat162float(h0));
    L0.y = __float2bfloat16_rn(v.y - __bfloat162float(h1));
    L1.x = __float2bfloat16_rn(v.z - __bfloat162float(h2));
    L1.y = __float2bfloat16_rn(v.w - __bfloat162float(h3));
    *(__nv_bfloat162*)(h + i)     = H0;
    *(__nv_bfloat162*)(h + i + 2) = H1;
    *(__nv_bfloat162*)(l + i)     = L0;
    *(__nv_bfloat162*)(l + i + 2) = L1;
}

__global__ __launch_bounds__(256)
void split3_kernel(const float* __restrict__ s0, const float* __restrict__ s1,
                   const float* __restrict__ s2,
                   __nv_bfloat16* __restrict__ h0, __nv_bfloat16* __restrict__ l0,
                   __nv_bfloat16* __restrict__ h1, __nv_bfloat16* __restrict__ l1,
                   __nv_bfloat16* __restrict__ h2, __nv_bfloat16* __restrict__ l2)
{
    long long i = ((long long)blockIdx.x * 256 + threadIdx.x) * 4;
    if (i >= N_QKV) return;
    const float* s = (blockIdx.y == 0) ? s0 : (blockIdx.y == 1) ? s1 : s2;
    __nv_bfloat16* h = (blockIdx.y == 0) ? h0 : (blockIdx.y == 1) ? h1 : h2;
    __nv_bfloat16* l = (blockIdx.y == 0) ? l0 : (blockIdx.y == 1) ? l1 : l2;
    split4(s, h, l, i);
}

__global__ __launch_bounds__(256)
void splitW_kernel(const float* __restrict__ wd, const float* __restrict__ wq,
                   const float* __restrict__ wk, const float* __restrict__ wv,
                   const float* __restrict__ wo,
                   __nv_bfloat16* __restrict__ wdh, __nv_bfloat16* __restrict__ wdl,
                   __nv_bfloat16* __restrict__ wqh, __nv_bfloat16* __restrict__ wql,
                   __nv_bfloat16* __restrict__ wkh, __nv_bfloat16* __restrict__ wkl,
                   __nv_bfloat16* __restrict__ wvh, __nv_bfloat16* __restrict__ wvl,
                   __nv_bfloat16* __restrict__ woh, __nv_bfloat16* __restrict__ wol)
{
    long long i = ((long long)blockIdx.x * 256 + threadIdx.x) * 4;
    const int y = blockIdx.y;
    const long long n = (y == 0) ? (long long)N_WD : (long long)N_W;
    if (i >= n) return;
    const float* s = (y == 0) ? wd : (y == 1) ? wq : (y == 2) ? wk : (y == 3) ? wv : wo;
    __nv_bfloat16* h = (y == 0) ? wdh : (y == 1) ? wqh : (y == 2) ? wkh : (y == 3) ? wvh : woh;
    __nv_bfloat16* l = (y == 0) ? wdl : (y == 1) ? wql : (y == 2) ? wkl : (y == 3) ? wvl : wol;
    split4(s, h, l, i);
}

// ---------------------------------------------------------------------------
// Row softmax over NKEYS, fp32 in -> split bf16 out. One block per row.
// ---------------------------------------------------------------------------
__global__ __launch_bounds__(256)
void softmax_split_kernel(const float* __restrict__ S,
                          __nv_bfloat16* __restrict__ Ph, __nv_bfloat16* __restrict__ Pl)
{
    const float* p = S + (long long)blockIdx.x * NKEYS;
    __nv_bfloat16* ph = Ph + (long long)blockIdx.x * NKEYS;
    __nv_bfloat16* pl = Pl + (long long)blockIdx.x * NKEYS;
    const int tid = threadIdx.x;

    float v[16];
    float m = __int_as_float(0xff800000);
#pragma unroll
    for (int i = 0; i < 16; i++) { v[i] = p[tid + i * 256]; m = fmaxf(m, v[i]); }

    __shared__ float red[256];
    red[tid] = m; __syncthreads();
#pragma unroll
    for (int s = 128; s > 0; s >>= 1) {
        if (tid < s) red[tid] = fmaxf(red[tid], red[tid + s]);
        __syncthreads();
    }
    m = red[0]; __syncthreads();

    float sum = 0.0f;
#pragma unroll
    for (int i = 0; i < 16; i++) { v[i] = __expf(v[i] - m); sum += v[i]; }
    red[tid] = sum; __syncthreads();
#pragma unroll
    for (int s = 128; s > 0; s >>= 1) {
        if (tid < s) red[tid] += red[tid + s];
        __syncthreads();
    }
    const float inv = 1.0f / red[0];
#pragma unroll
    for (int i = 0; i < 16; i++) {
        float pv = v[i] * inv;
        __nv_bfloat16 h = __float2bfloat16_rn(pv);
        ph[tid + i * 256] = h;
        pl[tid + i * 256] = __float2bfloat16_rn(pv - __bfloat162float(h));
    }
}

// ---------------------------------------------------------------------------
// Host dispatch
// ---------------------------------------------------------------------------
#define SMEM_NT (2 * (20480 + 2 * 64 * LDB_NT * 2))
#define SMEM_NN (2 * (20480 + 2 * 32 * LDB_NN * 2))

static void run_gemm3(const __nv_bfloat16* Ah, const __nv_bfloat16* Al,
                      const __nv_bfloat16* Bh, const __nv_bfloat16* Bl,
                      float* Cf, __nv_bfloat16* Ch, __nv_bfloat16* Cl,
                      int M, int N, int K,
                      long long sA, long long sB, long long sC, int batch,
                      bool transB,
                      const float* biasN, const float* biasM, float scale,
                      const int* mask, long long sMask)
{
    dim3 grid(N / 64, M / 128, batch), block(256);
    if (transB)
        gemm3_kernel<true><<<grid, block, SMEM_NT>>>(Ah, Al, Bh, Bl, Cf, Ch, Cl,
            M, N, K, sA, sB, sC, biasN, biasM, scale, mask, sMask);
    else
        gemm3_kernel<false><<<grid, block, SMEM_NN>>>(Ah, Al, Bh, Bl, Cf, Ch, Cl,
            M, N, K, sA, sB, sC, biasN, biasM, scale, mask, sMask);
}

extern "C" void kernel_launch(void* const* d_in, const int* in_sizes, int n_in,
                              void* d_out, int out_size)
{
    (void)in_sizes; (void)n_in; (void)out_size;

    const float* queries = (const float*)d_in[0];
    const float* keys    = (const float*)d_in[1];
    const float* values  = (const float*)d_in[2];
    const int*   mask    = (const int*)d_in[3];
    const float* Wq = (const float*)d_in[4];
    const float* bq = (const float*)d_in[5];
    const float* Wk = (const float*)d_in[6];
    const float* bk = (const float*)d_in[7];
    const float* Wv = (const float*)d_in[8];
    const float* bv = (const float*)d_in[9];
    const float* Wo = (const float*)d_in[10];
    const float* bo = (const float*)d_in[11];
    const float* Wd = (const float*)d_in[12];
    const float* bd = (const float*)d_in[13];
    float* out = (float*)d_out;

    cudaFuncSetAttribute(gemm3_kernel<true>,  cudaFuncAttributeMaxDynamicSharedMemorySize, SMEM_NT);
    cudaFuncSetAttribute(gemm3_kernel<false>, cudaFuncAttributeMaxDynamicSharedMemorySize, SMEM_NN);

    __nv_bfloat16 *qih,*qil,*kih,*kil,*vih,*vil,*wdh,*wdl,*wqh,*wql,*wkh,*wkl,*wvh,*wvl,*woh,*wol;
    __nv_bfloat16 *qdsh,*qdsl,*qh,*ql,*kh,*kl,*vh,*vl,*ph,*pl,*atth,*attl;
    float *sS;
    cudaGetSymbolAddress((void**)&qih, g_qih);   cudaGetSymbolAddress((void**)&qil, g_qil);
    cudaGetSymbolAddress((void**)&kih, g_kih);   cudaGetSymbolAddress((void**)&kil, g_kil);
    cudaGetSymbolAddress((void**)&vih, g_vih);   cudaGetSymbolAddress((void**)&vil, g_vil);
    cudaGetSymbolAddress((void**)&wdh, g_wdh);   cudaGetSymbolAddress((void**)&wdl, g_wdl);
    cudaGetSymbolAddress((void**)&wqh, g_wqh);   cudaGetSymbolAddress((void**)&wql, g_wql);
    cudaGetSymbolAddress((void**)&wkh, g_wkh);   cudaGetSymbolAddress((void**)&wkl, g_wkl);
    cudaGetSymbolAddress((void**)&wvh, g_wvh);   cudaGetSymbolAddress((void**)&wvl, g_wvl);
    cudaGetSymbolAddress((void**)&woh, g_woh);   cudaGetSymbolAddress((void**)&wol, g_wol);
    cudaGetSymbolAddress((void**)&qdsh, g_qdsh); cudaGetSymbolAddress((void**)&qdsl, g_qdsl);
    cudaGetSymbolAddress((void**)&qh, g_qh);     cudaGetSymbolAddress((void**)&ql, g_ql);
    cudaGetSymbolAddress((void**)&kh, g_kh);     cudaGetSymbolAddress((void**)&kl, g_kl);
    cudaGetSymbolAddress((void**)&vh, g_vh);     cudaGetSymbolAddress((void**)&vl, g_vl);
    cudaGetSymbolAddress((void**)&ph, g_ph);     cudaGetSymbolAddress((void**)&pl, g_pl);
    cudaGetSymbolAddress((void**)&atth, g_atth); cudaGetSymbolAddress((void**)&attl, g_attl);
    cudaGetSymbolAddress((void**)&sS, g_s);

    // splits: 2 launches
    {
        dim3 g3((N_QKV / 4 + 255) / 256, 3);
        split3_kernel<<<g3, 256>>>(queries, keys, values, qih, qil, kih, kil, vih, vil);
        dim3 gw((N_WD / 4 + 255) / 256, 5);
        splitW_kernel<<<gw, 256>>>(Wd, Wq, Wk, Wv, Wo,
                                   wdh, wdl, wqh, wql, wkh, wkl, wvh, wvl, woh, wol);
    }

    // 1. Downsample (NN): qds[b] = Wd @ queries[b] + bd (row bias)
    run_gemm3(wdh, wdl, qih, qil, nullptr, qdsh, qdsl,
              QAFT, DMODEL, QBEF,
              0, (long long)QBEF * DMODEL, (long long)QAFT * DMODEL, BATCH,
              false, nullptr, bd, 1.0f, nullptr, 0);

    // 2. Q projection (NT): q = qds @ Wq^T + bq
    run_gemm3(qdsh, qdsl, wqh, wql, nullptr, qh, ql,
              BATCH * QAFT, DMODEL, DMODEL, 0, 0, 0, 1,
              true, bq, nullptr, 1.0f, nullptr, 0);

    // 3. K projection
    run_gemm3(kih, kil, wkh, wkl, nullptr, kh, kl,
              BATCH * NKEYS, DMODEL, DMODEL, 0, 0, 0, 1,
              true, bk, nullptr, 1.0f, nullptr, 0);

    // 4. V projection
    run_gemm3(vih, vil, wvh, wvl, nullptr, vh, vl,
              BATCH * NKEYS, DMODEL, DMODEL, 0, 0, 0, 1,
              true, bv, nullptr, 1.0f, nullptr, 0);

    // 5. Scores (NT): s = (q @ k^T)/sqrt(512), masked -> -inf
    run_gemm3(qh, ql, kh, kl, sS, nullptr, nullptr,
              QAFT, NKEYS, DMODEL,
              (long long)QAFT * DMODEL, (long long)NKEYS * DMODEL,
              (long long)QAFT * NKEYS, BATCH,
              true, nullptr, nullptr, 0.044194173824159216f,
              mask, (long long)QAFT * NKEYS);

    // 6. Softmax -> split P
    softmax_split_kernel<<<BATCH * QAFT, 256>>>(sS, ph, pl);

    // 7. PV (NN): att[b] = P[b] @ v[b]
    run_gemm3(ph, pl, vh, vl, nullptr, atth, attl,
              QAFT, DMODEL, NKEYS,
              (long long)QAFT * NKEYS, (long long)NKEYS * DMODEL,
              (long long)QAFT * DMODEL, BATCH,
              false, nullptr, nullptr, 1.0f, nullptr, 0);

    // 8. Output projection (NT) -> fp32 d_out
    run_gemm3(atth, attl, woh, wol, out, nullptr, nullptr,
              BATCH * QAFT, DMODEL, DMODEL, 0, 0, 0, 1,
              true, bo, nullptr, 1.0f, nullptr, 0);
}